// round 5
// baseline (speedup 1.0000x reference)
#include <cuda_runtime.h>
#include <cuda_fp16.h>

#define BB   2048
#define SS   168
#define FF   7
#define HH   128
#define GG4  512
#define PP   96
#define AAT  135
#define BT   16
#define NCTA 128
#define NTHR 256
#define KB   8
#define HSTR 136
#define WSTR 140
#define HD   36
#define WSTAGE 4096

#define OFF_H    0
#define OFF_C    2176
#define OFF_Y    4352
#define OFF_HD   4480
#define OFF_CD   9088
#define OFF_WBUF 13696
#define OFF_BENC 21888
#define OFF_BDEC 22400
#define OFF_BATT 22912
#define OFF_WOUT 23088
#define OFF_MISC 23984
#define OFF_U    24016
#define XBS_OFF  OFF_U
#define WIH_OFF  (OFF_U + 18816)
#define WATT_OFF OFF_U
#define SCOR_OFF (OFF_U + SS * WSTR)
#define SMEM_FLOATS (OFF_U + SS * WSTR + BT * SS)
#define SMEM_BYTES  (SMEM_FLOATS * 4)

__device__ __half g_enc[(size_t)BB * SS * HH];

__device__ __forceinline__ unsigned long long pack2(float lo, float hi) {
    unsigned long long r;
    asm("mov.b64 %0, {%1, %2};" : "=l"(r) : "f"(lo), "f"(hi));
    return r;
}
__device__ __forceinline__ void unpack2(unsigned long long v, float &lo, float &hi) {
    asm("mov.b64 {%0, %1}, %2;" : "=f"(lo), "=f"(hi) : "l"(v));
}
__device__ __forceinline__ void fma2(unsigned long long &d, unsigned long long a, unsigned long long b) {
    asm("fma.rn.f32x2 %0, %1, %2, %0;" : "+l"(d) : "l"(a), "l"(b));
}
__device__ __forceinline__ float sigf(float x) { return __fdividef(1.f, 1.f + __expf(-x)); }
__device__ __forceinline__ float tanh_f(float x) {
    float ax = fabsf(x);
    float t  = __expf(-2.f * ax);
    return copysignf(__fdividef(1.f - t, 1.f + t), x);
}

// acc[gt][bi] (f32x2 over gate pair (g,g+64)) += W[rows] @ hdup.
// Weight smem rows r = gt*64+gg hold interleaved pairs (W[g],W[g+64]) per k,
// 4x 16B units per row, XOR-swizzled by (r>>1)&3. hdup[k] holds per-batch
// duplicated (h,h) pairs in permuted order (4*(b&3)+(b>>2)).
template<int NGT>
__device__ __forceinline__ void gemm_accum(const float* __restrict__ Wg,
                                           const float* __restrict__ hd,
                                           unsigned long long (*acc)[4],
                                           float* __restrict__ wbuf,
                                           int tid, int gg, int bg, int sw)
{
    float2 lo[NGT], hi[NGT];
    #pragma unroll
    for (int q = 0; q < NGT; ++q) {
        int t = tid + NTHR * q, r = t >> 2, u = t & 3;
        int gl = ((r >> 6) << 7) + (r & 63);
        lo[q] = *(const float2*)(Wg + gl * HH + 2 * u);
        hi[q] = *(const float2*)(Wg + (gl + 64) * HH + 2 * u);
    }
    #pragma unroll
    for (int q = 0; q < NGT; ++q) {
        int t = tid + NTHR * q, r = t >> 2, u = t & 3;
        int up = u ^ ((r >> 1) & 3);
        *(float4*)(wbuf + r * 16 + up * 4) = make_float4(lo[q].x, hi[q].x, lo[q].y, hi[q].y);
    }
    __syncthreads();

    for (int c = 0; c < HH / KB; ++c) {
        if (c < HH / KB - 1) {
            #pragma unroll
            for (int q = 0; q < NGT; ++q) {
                int t = tid + NTHR * q, r = t >> 2, u = t & 3;
                int gl = ((r >> 6) << 7) + (r & 63);
                lo[q] = *(const float2*)(Wg + gl * HH + (c + 1) * KB + 2 * u);
                hi[q] = *(const float2*)(Wg + (gl + 64) * HH + (c + 1) * KB + 2 * u);
            }
        }
        const float* wb = wbuf + (c & 1) * WSTAGE;
        const int k0 = c * KB;
        #pragma unroll
        for (int kk = 0; kk < KB; kk += 4) {
            ulonglong2 hA[4], hB[4];
            #pragma unroll
            for (int k = 0; k < 4; ++k) {
                const float* hp = hd + (k0 + kk + k) * HD + bg * 8;
                hA[k] = *(const ulonglong2*)(hp);
                hB[k] = *(const ulonglong2*)(hp + 4);
            }
            const int u0 = kk >> 1;
            #pragma unroll
            for (int gt = 0; gt < NGT; ++gt) {
                const float* wr = wb + (gt * 64 + gg) * 16;
                ulonglong2 wA = *(const ulonglong2*)(wr + ((u0    ) ^ sw) * 4);
                ulonglong2 wB = *(const ulonglong2*)(wr + ((u0 + 1) ^ sw) * 4);
                fma2(acc[gt][0], wA.x, hA[0].x); fma2(acc[gt][1], wA.x, hA[0].y);
                fma2(acc[gt][2], wA.x, hB[0].x); fma2(acc[gt][3], wA.x, hB[0].y);
                fma2(acc[gt][0], wA.y, hA[1].x); fma2(acc[gt][1], wA.y, hA[1].y);
                fma2(acc[gt][2], wA.y, hB[1].x); fma2(acc[gt][3], wA.y, hB[1].y);
                fma2(acc[gt][0], wB.x, hA[2].x); fma2(acc[gt][1], wB.x, hA[2].y);
                fma2(acc[gt][2], wB.x, hB[2].x); fma2(acc[gt][3], wB.x, hB[2].y);
                fma2(acc[gt][0], wB.y, hA[3].x); fma2(acc[gt][1], wB.y, hA[3].y);
                fma2(acc[gt][2], wB.y, hB[3].x); fma2(acc[gt][3], wB.y, hB[3].y);
            }
        }
        if (c < HH / KB - 1) {
            float* wbn = wbuf + ((c + 1) & 1) * WSTAGE;
            #pragma unroll
            for (int q = 0; q < NGT; ++q) {
                int t = tid + NTHR * q, r = t >> 2, u = t & 3;
                int up = u ^ ((r >> 1) & 3);
                *(float4*)(wbn + r * 16 + up * 4) = make_float4(lo[q].x, hi[q].x, lo[q].y, hi[q].y);
            }
        }
        __syncthreads();
    }
}

extern "C" __global__ void __launch_bounds__(NTHR, 1)
edk_kernel(const float* __restrict__ xb,
           const float* __restrict__ Wih_e, const float* __restrict__ Whh_e,
           const float* __restrict__ bih_e, const float* __restrict__ bhh_e,
           const float* __restrict__ Watt,  const float* __restrict__ batt,
           const float* __restrict__ Wih_d, const float* __restrict__ Whh_d,
           const float* __restrict__ bih_d, const float* __restrict__ bhh_d,
           const float* __restrict__ Wout,  const float* __restrict__ bout,
           const float* __restrict__ Wfin,  const float* __restrict__ bfin,
           float* __restrict__ out)
{
    extern __shared__ float sm[];
    const int tid = threadIdx.x;
    const int gg  = tid >> 2;
    const int bg  = tid & 3;
    const int sw  = (gg >> 1) & 3;
    const int b0  = blockIdx.x * BT;

    float* h_s    = sm + OFF_H;
    float* c_s    = sm + OFF_C;     // decoder: combine staging
    float* y_s    = sm + OFF_Y;
    float* hd     = sm + OFF_HD;    // duplicated-pair h
    float* cd     = sm + OFF_CD;    // duplicated-pair combine
    float* wbuf   = sm + OFF_WBUF;
    float* benc_s = sm + OFF_BENC;
    float* bdec_s = sm + OFF_BDEC;
    float* batt_s = sm + OFF_BATT;
    float* wout_s = sm + OFF_WOUT;
    float* wfin_s = sm + OFF_MISC;
    float* bout_s = sm + OFF_MISC + 8;
    float* bfin_s = sm + OFF_MISC + 16;
    float* xbs    = sm + XBS_OFF;
    float* wih_s  = sm + WIH_OFF;
    float* watt_s = sm + WATT_OFF;
    float* scor_s = sm + SCOR_OFF;

    for (int i = tid; i < BT * SS * FF; i += NTHR) {
        int b = i / (SS * FF), r = i % (SS * FF);
        xbs[b * 1176 + r] = xb[(size_t)(b0 + b) * (SS * FF) + r];
    }
    for (int i = tid; i < GG4; i += NTHR) {
        benc_s[i] = bih_e[i] + bhh_e[i];
        bdec_s[i] = bih_d[i] + bhh_d[i];
    }
    for (int i = tid; i < GG4 * FF; i += NTHR) {
        int g = i / FF, f = i % FF;
        wih_s[g * 8 + f] = Wih_e[i];
    }
    for (int i = tid; i < GG4; i += NTHR) wih_s[i * 8 + 7] = 0.f;
    for (int i = tid; i < HH * HD; i += NTHR) hd[i] = 0.f;
    for (int i = tid; i < BT * HSTR; i += NTHR) h_s[i] = 0.f;
    for (int i = tid; i < SS; i += NTHR) batt_s[i] = batt[i];
    for (int i = tid; i < FF * HH; i += NTHR) wout_s[i] = Wout[i];
    if (tid < FF) { wfin_s[tid] = Wfin[tid]; bout_s[tid] = bout[tid]; }
    if (tid == 0) bfin_s[0] = bfin[0];
    __syncthreads();

    float creg[2][4];
    #pragma unroll
    for (int jj = 0; jj < 2; ++jj)
        #pragma unroll
        for (int bi = 0; bi < 4; ++bi) creg[jj][bi] = 0.f;

    // -------- encoder: 168 LSTM steps --------
    for (int s = 0; s < SS; ++s) {
        float afL[4][4], afH[4][4];
        #pragma unroll
        for (int gt = 0; gt < 4; ++gt) {
            float bL = benc_s[gt * 128 + gg];
            float bH = benc_s[gt * 128 + gg + 64];
            #pragma unroll
            for (int bi = 0; bi < 4; ++bi) { afL[gt][bi] = bL; afH[gt][bi] = bH; }
        }
        #pragma unroll
        for (int f = 0; f < FF; ++f) {
            float xv[4];
            #pragma unroll
            for (int bi = 0; bi < 4; ++bi)
                xv[bi] = xbs[(bg + 4 * bi) * 1176 + s * FF + f];
            #pragma unroll
            for (int gt = 0; gt < 4; ++gt) {
                float wL = wih_s[(gt * 128 + gg) * 8 + f];
                float wH = wih_s[(gt * 128 + gg + 64) * 8 + f];
                #pragma unroll
                for (int bi = 0; bi < 4; ++bi) {
                    afL[gt][bi] += wL * xv[bi];
                    afH[gt][bi] += wH * xv[bi];
                }
            }
        }
        unsigned long long acc[4][4];
        #pragma unroll
        for (int gt = 0; gt < 4; ++gt)
            #pragma unroll
            for (int bi = 0; bi < 4; ++bi) acc[gt][bi] = pack2(afL[gt][bi], afH[gt][bi]);

        gemm_accum<4>(Whh_e, hd, acc, wbuf, tid, gg, bg, sw);

        #pragma unroll
        for (int gt = 0; gt < 4; ++gt)
            #pragma unroll
            for (int bi = 0; bi < 4; ++bi) unpack2(acc[gt][bi], afL[gt][bi], afH[gt][bi]);

        #pragma unroll
        for (int bi = 0; bi < 4; ++bi) {
            int b = bg + 4 * bi;
            #pragma unroll
            for (int jj = 0; jj < 2; ++jj) {
                int j = gg + 64 * jj;
                float iv = sigf(jj ? afH[0][bi] : afL[0][bi]);
                float fv = sigf(jj ? afH[1][bi] : afL[1][bi]);
                float gv = tanh_f(jj ? afH[2][bi] : afL[2][bi]);
                float ov = sigf(jj ? afH[3][bi] : afL[3][bi]);
                float cc = fv * creg[jj][bi] + iv * gv;
                float hh = ov * tanh_f(cc);
                creg[jj][bi] = cc;
                *(float2*)(hd + j * HD + 8 * bg + 2 * bi) = make_float2(hh, hh);
                g_enc[(((size_t)(b0 + b)) * SS + s) * HH + j] = __float2half_rn(hh);
                if (s == SS - 1) h_s[b * HSTR + j] = hh;
            }
        }
        __syncthreads();
    }

    // y0 = xb[:, -1, :], then overwrite union with W_att
    for (int i = tid; i < BT * 8; i += NTHR) {
        int b = i >> 3, f = i & 7;
        y_s[i] = (f < FF) ? xbs[b * 1176 + (SS - 1) * FF + f] : 0.f;
    }
    __syncthreads();
    for (int i = tid; i < SS * WSTR; i += NTHR) {
        int s_ = i / WSTR, a_ = i % WSTR;
        watt_s[i] = (a_ < AAT) ? Watt[s_ * AAT + a_] : 0.f;
    }
    __syncthreads();

    // -------- decoder: 96 steps --------
    for (int p = 0; p < PP; ++p) {
        // 1) scores = [prev_h | y_prev] @ W_att^T + b_att
        {
            int b = tid >> 4, ts = tid & 15;
            float acs[11];
            #pragma unroll
            for (int si = 0; si < 11; ++si) acs[si] = 0.f;
            #pragma unroll 2
            for (int a4 = 0; a4 < 34; ++a4) {
                float4 av;
                if (a4 < 32) av = *(const float4*)(h_s + b * HSTR + a4 * 4);
                else         av = *(const float4*)(y_s + b * 8 + (a4 - 32) * 4);
                #pragma unroll
                for (int si = 0; si < 11; ++si) {
                    int s_ = ts + 16 * si;
                    if (s_ < SS) {
                        float4 wv = *(const float4*)(watt_s + s_ * WSTR + a4 * 4);
                        acs[si] += av.x * wv.x + av.y * wv.y + av.z * wv.z + av.w * wv.w;
                    }
                }
            }
            #pragma unroll
            for (int si = 0; si < 11; ++si) {
                int s_ = ts + 16 * si;
                if (s_ < SS) scor_s[b * SS + s_] = acs[si] + batt_s[s_];
            }
        }
        __syncthreads();

        // 2) softmax (warp = 2 rows, 16-lane halves)
        {
            int w = tid >> 5, lane = tid & 31;
            int b = 2 * w + (lane >> 4), l = lane & 15;
            float mx = -1e30f;
            for (int s_ = l; s_ < SS; s_ += 16) mx = fmaxf(mx, scor_s[b * SS + s_]);
            #pragma unroll
            for (int o = 8; o >= 1; o >>= 1) mx = fmaxf(mx, __shfl_xor_sync(0xffffffffu, mx, o));
            float sum = 0.f;
            for (int s_ = l; s_ < SS; s_ += 16) {
                float e = __expf(scor_s[b * SS + s_] - mx);
                scor_s[b * SS + s_] = e;
                sum += e;
            }
            #pragma unroll
            for (int o = 8; o >= 1; o >>= 1) sum += __shfl_xor_sync(0xffffffffu, sum, o);
            float inv = __fdividef(1.f, sum);
            for (int s_ = l; s_ < SS; s_ += 16) scor_s[b * SS + s_] *= inv;
        }
        __syncthreads();

        // 3) combine = attn_w @ enc_out  (fp16 L2-resident reads)
        {
            int b = tid >> 4, hq = tid & 15;
            const __half* ep = g_enc + (((size_t)(b0 + b)) * SS) * HH + hq * 8;
            float acm[8];
            #pragma unroll
            for (int q = 0; q < 8; ++q) acm[q] = 0.f;
            #pragma unroll 8
            for (int s_ = 0; s_ < SS; ++s_) {
                float w = scor_s[b * SS + s_];
                uint4 v = *(const uint4*)(ep + (size_t)s_ * HH);
                __half2* hp = (__half2*)&v;
                #pragma unroll
                for (int q = 0; q < 4; ++q) {
                    float2 f2 = __half22float2(hp[q]);
                    acm[2 * q]     += w * f2.x;
                    acm[2 * q + 1] += w * f2.y;
                }
            }
            #pragma unroll
            for (int q = 0; q < 4; ++q)
                *(float2*)(c_s + b * HSTR + hq * 8 + 2 * q) = make_float2(acm[2*q], acm[2*q+1]);
        }
        __syncthreads();

        // 3b) transpose combine into duplicated-pair layout
        #pragma unroll
        for (int bi = 0; bi < 4; ++bi) {
            int b = bg + 4 * bi;
            float v0 = c_s[b * HSTR + gg];
            float v1 = c_s[b * HSTR + gg + 64];
            *(float2*)(cd + gg * HD + 8 * bg + 2 * bi) = make_float2(v0, v0);
            *(float2*)(cd + (gg + 64) * HD + 8 * bg + 2 * bi) = make_float2(v1, v1);
        }

        // 4) gates (i/f/g only)
        unsigned long long acc[3][4];
        #pragma unroll
        for (int gt = 0; gt < 3; ++gt) {
            float bL = bdec_s[gt * 128 + gg];
            float bH = bdec_s[gt * 128 + gg + 64];
            #pragma unroll
            for (int bi = 0; bi < 4; ++bi) acc[gt][bi] = pack2(bL, bH);
        }
        gemm_accum<3>(Wih_d, cd, acc, wbuf, tid, gg, bg, sw);
        gemm_accum<3>(Whh_d, hd, acc, wbuf, tid, gg, bg, sw);

        // 5) c_new = sig(f)*prev_h + sig(i)*tanh(g); carry h := c_new
        #pragma unroll
        for (int bi = 0; bi < 4; ++bi) {
            int b = bg + 4 * bi;
            #pragma unroll
            for (int jj = 0; jj < 2; ++jj) {
                int j = gg + 64 * jj;
                float iL, iH, fL, fH, gL, gH;
                unpack2(acc[0][bi], iL, iH);
                unpack2(acc[1][bi], fL, fH);
                unpack2(acc[2][bi], gL, gH);
                float iv = sigf(jj ? iH : iL);
                float fv = sigf(jj ? fH : fL);
                float gv = tanh_f(jj ? gH : gL);
                float cn = fv * h_s[b * HSTR + j] + iv * gv;
                h_s[b * HSTR + j] = cn;
                *(float2*)(hd + j * HD + 8 * bg + 2 * bi) = make_float2(cn, cn);
            }
        }
        __syncthreads();

        // 6) out = c_new @ W_out^T + b_out; final = out @ W_fin + b_fin
        if (tid < BT * FF) {
            int b = tid / FF, f = tid % FF;
            float a = 0.f;
            #pragma unroll
            for (int j4 = 0; j4 < 32; ++j4) {
                float4 cv = *(const float4*)(h_s + b * HSTR + j4 * 4);
                float4 wv = *(const float4*)(wout_s + f * HH + j4 * 4);
                a += cv.x * wv.x + cv.y * wv.y + cv.z * wv.z + cv.w * wv.w;
            }
            y_s[b * 8 + f] = a + bout_s[f];
        }
        __syncthreads();
        if (tid < BT) {
            float a = bfin_s[0];
            #pragma unroll
            for (int f = 0; f < FF; ++f) a += y_s[tid * 8 + f] * wfin_s[f];
            out[(size_t)(b0 + tid) * PP + p] = a;
        }
        __syncthreads();
    }
}

extern "C" void kernel_launch(void* const* d_in, const int* in_sizes, int n_in,
                              void* d_out, int out_size)
{
    (void)in_sizes; (void)n_in; (void)out_size;
    cudaFuncSetAttribute(edk_kernel, cudaFuncAttributeMaxDynamicSharedMemorySize, SMEM_BYTES);
    edk_kernel<<<NCTA, NTHR, SMEM_BYTES>>>(
        (const float*)d_in[0],  (const float*)d_in[1],  (const float*)d_in[2],
        (const float*)d_in[3],  (const float*)d_in[4],  (const float*)d_in[5],
        (const float*)d_in[6],  (const float*)d_in[7],  (const float*)d_in[8],
        (const float*)d_in[9],  (const float*)d_in[10], (const float*)d_in[11],
        (const float*)d_in[12], (const float*)d_in[13], (const float*)d_in[14],
        (float*)d_out);
}

// round 11
// speedup vs baseline: 1.7169x; 1.7169x over previous
#include <cuda_runtime.h>
#include <cuda_fp16.h>
#include <cstdint>
#include <cstddef>

#define BB   2048
#define SS   168
#define FF   7
#define HH   128
#define GG4  512
#define PP   96
#define AAT  135
#define BT   16
#define NCTA 128
#define NTHR 256
#define KB   8
#define WPAD 12
#define HSTR 136
#define WSTR 140

// smem float offsets
#define OFF_HS    0
#define OFF_CS    2176
#define OFF_YS    4352
#define OFF_BDEC  4480
#define OFF_BATT  4992
#define OFF_WOUT  5168
#define OFF_MISC  6064
// union base @ 6144
#define OFF_STAGE 6144              /* enc: 512*17 fp32 */
#define OFF_HSM   14848             /* enc: 16*136 fp16 = 1088 fl */
#define OFF_WIH   15936             /* enc: 512*9 fp32 */
#define OFF_XBS   20544             /* enc: 16*1176 fp32 */
#define OFF_WBUF  6144              /* dec: 2*512*12 */
#define OFF_WATT  18432             /* dec: 168*140 */
#define OFF_SCOR  41952             /* dec: 16*168 */
#define SMEM_FLOATS 44640
#define SMEM_BYTES  (SMEM_FLOATS * 4)

static __device__ __half g_enc[(size_t)BB * SS * HH];

__device__ __forceinline__ float sigf(float x) { return __fdividef(1.f, 1.f + __expf(-x)); }
__device__ __forceinline__ float tanh_f(float x) {
    float ax = fabsf(x);
    float t  = __expf(-2.f * ax);
    return copysignf(__fdividef(1.f - t, 1.f + t), x);
}

__device__ __forceinline__ uint32_t f2h2(float lo, float hi) {
    __half2 h = __floats2half2_rn(lo, hi);
    return *reinterpret_cast<uint32_t*>(&h);
}

__device__ __forceinline__ void mma16816(float* c, const uint32_t* a, uint32_t b0, uint32_t b1) {
    asm volatile(
        "mma.sync.aligned.m16n8k16.row.col.f32.f16.f16.f32 "
        "{%0,%1,%2,%3}, {%4,%5,%6,%7}, {%8,%9}, {%0,%1,%2,%3};"
        : "+f"(c[0]), "+f"(c[1]), "+f"(c[2]), "+f"(c[3])
        : "r"(a[0]), "r"(a[1]), "r"(a[2]), "r"(a[3]), "r"(b0), "r"(b1));
}

__device__ __forceinline__ unsigned long long pack2(float lo, float hi) {
    unsigned long long r;
    asm("mov.b64 %0, {%1, %2};" : "=l"(r) : "f"(lo), "f"(hi));
    return r;
}
__device__ __forceinline__ void unpack2(unsigned long long v, float &lo, float &hi) {
    asm("mov.b64 {%0, %1}, %2;" : "=f"(lo), "=f"(hi) : "l"(v));
}
__device__ __forceinline__ void fma2(unsigned long long &d, unsigned long long a, unsigned long long b) {
    asm("fma.rn.f32x2 %0, %1, %2, %0;" : "+l"(d) : "l"(a), "l"(b));
}

// ---- decoder scalar GEMM (round-2, proven) ----
template<int NGI, int GR>
__device__ __forceinline__ void gemm_accum(const float* __restrict__ Wg,
                                           const float* __restrict__ As,
                                           unsigned long long (*acc)[2],
                                           float* __restrict__ wbuf,
                                           int tid, int gg, int bg)
{
    constexpr int NC = HH / KB;
    constexpr int NL = GR / 128;
    float4 st[4];
    #pragma unroll
    for (int q = 0; q < NL; ++q) {
        int i = tid + NTHR * q;
        int g = i >> 1;
        int kq = i & 1;
        st[q] = *(const float4*)(Wg + g * HH + kq * 4);
    }
    #pragma unroll
    for (int q = 0; q < NL; ++q) {
        int i = tid + NTHR * q;
        int g = i >> 1;
        int kq = i & 1;
        *(float4*)(wbuf + g * WPAD + kq * 4) = st[q];
    }
    __syncthreads();

    #pragma unroll 2
    for (int c = 0; c < NC; ++c) {
        if (c + 1 < NC) {
            #pragma unroll
            for (int q = 0; q < NL; ++q) {
                int i = tid + NTHR * q;
                int g = i >> 1;
                int kq = i & 1;
                st[q] = *(const float4*)(Wg + g * HH + (c + 1) * KB + kq * 4);
            }
        }
        const float* wb = wbuf + (c & 1) * (GG4 * WPAD);
        const int k0 = c * KB;
        #pragma unroll
        for (int kk = 0; kk < KB; kk += 4) {
            float4 hv0 = *(const float4*)(As + (bg     ) * HSTR + k0 + kk);
            float4 hv1 = *(const float4*)(As + (bg + 4 ) * HSTR + k0 + kk);
            float4 hv2 = *(const float4*)(As + (bg + 8 ) * HSTR + k0 + kk);
            float4 hv3 = *(const float4*)(As + (bg + 12) * HSTR + k0 + kk);
            unsigned long long hp0[4];
            unsigned long long hp1[4];
            hp0[0] = pack2(hv0.x, hv1.x);
            hp0[1] = pack2(hv0.y, hv1.y);
            hp0[2] = pack2(hv0.z, hv1.z);
            hp0[3] = pack2(hv0.w, hv1.w);
            hp1[0] = pack2(hv2.x, hv3.x);
            hp1[1] = pack2(hv2.y, hv3.y);
            hp1[2] = pack2(hv2.z, hv3.z);
            hp1[3] = pack2(hv2.w, hv3.w);
            #pragma unroll
            for (int gi = 0; gi < NGI; ++gi) {
                float4 wv = *(const float4*)(wb + (gg + 64 * gi) * WPAD + kk);
                unsigned long long w0 = pack2(wv.x, wv.x);
                unsigned long long w1 = pack2(wv.y, wv.y);
                unsigned long long w2 = pack2(wv.z, wv.z);
                unsigned long long w3 = pack2(wv.w, wv.w);
                fma2(acc[gi][0], w0, hp0[0]);
                fma2(acc[gi][1], w0, hp1[0]);
                fma2(acc[gi][0], w1, hp0[1]);
                fma2(acc[gi][1], w1, hp1[1]);
                fma2(acc[gi][0], w2, hp0[2]);
                fma2(acc[gi][1], w2, hp1[2]);
                fma2(acc[gi][0], w3, hp0[3]);
                fma2(acc[gi][1], w3, hp1[3]);
            }
        }
        if (c + 1 < NC) {
            float* wbn = wbuf + ((c + 1) & 1) * (GG4 * WPAD);
            #pragma unroll
            for (int q = 0; q < NL; ++q) {
                int i = tid + NTHR * q;
                int g = i >> 1;
                int kq = i & 1;
                *(float4*)(wbn + g * WPAD + kq * 4) = st[q];
            }
        }
        __syncthreads();
    }
}

// ---- main kernel ----
extern "C" __global__ void __launch_bounds__(NTHR, 1)
edk_kernel(const float* __restrict__ xb,
           const float* __restrict__ Wih_e, const float* __restrict__ Whh_e,
           const float* __restrict__ bih_e, const float* __restrict__ bhh_e,
           const float* __restrict__ Watt,  const float* __restrict__ batt,
           const float* __restrict__ Wih_d, const float* __restrict__ Whh_d,
           const float* __restrict__ bih_d, const float* __restrict__ bhh_d,
           const float* __restrict__ Wout,  const float* __restrict__ bout,
           const float* __restrict__ Wfin,  const float* __restrict__ bfin,
           float* __restrict__ out)
{
    extern __shared__ float sm[];
    const int tid = threadIdx.x;
    const int wid = tid >> 5;
    const int lane = tid & 31;
    const int gid = lane >> 2;
    const int tig = lane & 3;
    const int b0 = blockIdx.x * BT;

    float* h_s    = sm + OFF_HS;
    float* c_s    = sm + OFF_CS;
    float* y_s    = sm + OFF_YS;
    float* bdec_s = sm + OFF_BDEC;
    float* batt_s = sm + OFF_BATT;
    float* wout_s = sm + OFF_WOUT;
    float* wfin_s = sm + OFF_MISC;
    float* bout_s = sm + OFF_MISC + 8;
    float* bfin_s = sm + OFF_MISC + 16;
    float* stage  = sm + OFF_STAGE;
    __half* hsm   = (__half*)(sm + OFF_HSM);
    float* wih_s  = sm + OFF_WIH;
    float* xbs    = sm + OFF_XBS;

    // init loads
    for (int i = tid; i < BT * SS * FF; i += NTHR) {
        int b = i / (SS * FF);
        int r = i - b * (SS * FF);
        xbs[b * 1176 + r] = xb[(size_t)(b0 + b) * (SS * FF) + r];
    }
    for (int i = tid; i < GG4; i += NTHR) {
        #pragma unroll
        for (int f = 0; f < FF; ++f) {
            wih_s[i * 9 + f] = Wih_e[i * FF + f];
        }
        wih_s[i * 9 + 7] = bih_e[i] + bhh_e[i];
        bdec_s[i] = bih_d[i] + bhh_d[i];
    }
    for (int i = tid; i < 1088; i += NTHR) {
        ((float*)hsm)[i] = 0.f;
    }
    for (int i = tid; i < SS; i += NTHR) {
        batt_s[i] = batt[i];
    }
    for (int i = tid; i < FF * HH; i += NTHR) {
        wout_s[i] = Wout[i];
    }
    if (tid < FF) {
        wfin_s[tid] = Wfin[tid];
        bout_s[tid] = bout[tid];
    }
    if (tid == 0) {
        bfin_s[0] = bfin[0];
    }
    for (int i = tid; i < BT * 8; i += NTHR) {
        int b = i >> 3;
        int f = i & 7;
        y_s[i] = (f < FF) ? xb[(size_t)(b0 + b) * (SS * FF) + (SS - 1) * FF + f] : 0.f;
    }

    // A fragments: Whh (fp16) resident in registers. Warp owns rows [wid*64, wid*64+64).
    uint32_t afr[4][8][4];
    #pragma unroll
    for (int mt = 0; mt < 4; ++mt) {
        #pragma unroll
        for (int kt = 0; kt < 8; ++kt) {
            int r0 = wid * 64 + mt * 16 + gid;
            int c0 = kt * 16 + tig * 2;
            float2 v00 = *(const float2*)(Whh_e + (size_t)(r0    ) * HH + c0    );
            float2 v10 = *(const float2*)(Whh_e + (size_t)(r0 + 8) * HH + c0    );
            float2 v01 = *(const float2*)(Whh_e + (size_t)(r0    ) * HH + c0 + 8);
            float2 v11 = *(const float2*)(Whh_e + (size_t)(r0 + 8) * HH + c0 + 8);
            afr[mt][kt][0] = f2h2(v00.x, v00.y);
            afr[mt][kt][1] = f2h2(v10.x, v10.y);
            afr[mt][kt][2] = f2h2(v01.x, v01.y);
            afr[mt][kt][3] = f2h2(v11.x, v11.y);
        }
    }
    __syncthreads();

    // ---- encoder: 168 HMMA LSTM steps ----
    const int aj = tid >> 1;
    const int bh = (tid & 1) << 3;
    float creg[8];
    #pragma unroll
    for (int q = 0; q < 8; ++q) {
        creg[q] = 0.f;
    }

    for (int s = 0; s < SS; ++s) {
        float acc[4][2][4];
        #pragma unroll
        for (int mt = 0; mt < 4; ++mt) {
            #pragma unroll
            for (int nt = 0; nt < 2; ++nt) {
                #pragma unroll
                for (int q = 0; q < 4; ++q) {
                    acc[mt][nt][q] = 0.f;
                }
            }
        }
        #pragma unroll
        for (int kt = 0; kt < 8; ++kt) {
            int kb = kt * 16 + tig * 2;
            uint32_t bA0 = *(const uint32_t*)(hsm + (gid    ) * 136 + kb    );
            uint32_t bA1 = *(const uint32_t*)(hsm + (gid    ) * 136 + kb + 8);
            uint32_t bB0 = *(const uint32_t*)(hsm + (gid + 8) * 136 + kb    );
            uint32_t bB1 = *(const uint32_t*)(hsm + (gid + 8) * 136 + kb + 8);
            #pragma unroll
            for (int mt = 0; mt < 4; ++mt) {
                mma16816(acc[mt][0], afr[mt][kt], bA0, bA1);
                mma16816(acc[mt][1], afr[mt][kt], bB0, bB1);
            }
        }
        // stage out: D rows = gate rows (natural order), cols = batch
        #pragma unroll
        for (int mt = 0; mt < 4; ++mt) {
            #pragma unroll
            for (int nt = 0; nt < 2; ++nt) {
                int g0 = wid * 64 + mt * 16 + gid;
                int bb = nt * 8 + tig * 2;
                stage[g0 * 17 + bb]           = acc[mt][nt][0];
                stage[g0 * 17 + bb + 1]       = acc[mt][nt][1];
                stage[(g0 + 8) * 17 + bb]     = acc[mt][nt][2];
                stage[(g0 + 8) * 17 + bb + 1] = acc[mt][nt][3];
            }
        }
        __syncthreads();

        // activation: thread handles j=aj, batches bh..bh+7
        #pragma unroll
        for (int bi = 0; bi < 8; ++bi) {
            int b = bh + bi;
            float xf[7];
            #pragma unroll
            for (int f = 0; f < FF; ++f) {
                xf[f] = xbs[b * 1176 + s * FF + f];
            }
            float pre[4];
            #pragma unroll
            for (int gt = 0; gt < 4; ++gt) {
                const float* wr = wih_s + (gt * 128 + aj) * 9;
                float a = wr[7];
                #pragma unroll
                for (int f = 0; f < FF; ++f) {
                    a += wr[f] * xf[f];
                }
                pre[gt] = a + stage[(gt * 128 + aj) * 17 + b];
            }
            float cc = sigf(pre[1]) * creg[bi] + sigf(pre[0]) * tanh_f(pre[2]);
            float hh = sigf(pre[3]) * tanh_f(cc);
            creg[bi] = cc;
            hsm[b * 136 + aj] = __float2half_rn(hh);
            g_enc[((size_t)(b0 + b) * SS + s) * HH + aj] = __float2half_rn(hh);
            if (s == SS - 1) {
                h_s[b * HSTR + aj] = hh;
            }
        }
        __syncthreads();
    }

    // ---- switch union to decoder layout ----
    float* watt_s = sm + OFF_WATT;
    float* scor_s = sm + OFF_SCOR;
    float* wbuf   = sm + OFF_WBUF;
    for (int i = tid; i < SS * WSTR; i += NTHR) {
        int s_ = i / WSTR;
        int a_ = i - s_ * WSTR;
        watt_s[i] = (a_ < AAT) ? Watt[s_ * AAT + a_] : 0.f;
    }
    __syncthreads();

    const int gg = tid >> 2;
    const int bg = tid & 3;

    // ---- decoder: 96 steps ----
    for (int p = 0; p < PP; ++p) {
        {
            int b = tid >> 4;
            int ts = tid & 15;
            float acs[11];
            #pragma unroll
            for (int si = 0; si < 11; ++si) {
                acs[si] = 0.f;
            }
            #pragma unroll 2
            for (int a4 = 0; a4 < 34; ++a4) {
                float4 av;
                if (a4 < 32) {
                    av = *(const float4*)(h_s + b * HSTR + a4 * 4);
                } else {
                    av = *(const float4*)(y_s + b * 8 + (a4 - 32) * 4);
                }
                #pragma unroll
                for (int si = 0; si < 11; ++si) {
                    int s_ = ts + 16 * si;
                    if (s_ < SS) {
                        float4 wv = *(const float4*)(watt_s + s_ * WSTR + a4 * 4);
                        acs[si] += av.x * wv.x + av.y * wv.y + av.z * wv.z + av.w * wv.w;
                    }
                }
            }
            #pragma unroll
            for (int si = 0; si < 11; ++si) {
                int s_ = ts + 16 * si;
                if (s_ < SS) {
                    scor_s[b * SS + s_] = acs[si] + batt_s[s_];
                }
            }
        }
        __syncthreads();

        {
            int b = 2 * wid + (lane >> 4);
            int l16 = lane & 15;
            float mx = -1e30f;
            for (int s_ = l16; s_ < SS; s_ += 16) {
                mx = fmaxf(mx, scor_s[b * SS + s_]);
            }
            #pragma unroll
            for (int o = 8; o >= 1; o >>= 1) {
                mx = fmaxf(mx, __shfl_xor_sync(0xffffffffu, mx, o));
            }
            float sum = 0.f;
            for (int s_ = l16; s_ < SS; s_ += 16) {
                float e = __expf(scor_s[b * SS + s_] - mx);
                scor_s[b * SS + s_] = e;
                sum += e;
            }
            #pragma unroll
            for (int o = 8; o >= 1; o >>= 1) {
                sum += __shfl_xor_sync(0xffffffffu, sum, o);
            }
            float inv = __fdividef(1.f, sum);
            for (int s_ = l16; s_ < SS; s_ += 16) {
                scor_s[b * SS + s_] *= inv;
            }
        }
        __syncthreads();

        {
            int b = tid >> 4;
            int hq = tid & 15;
            const __half* ep = g_enc + ((size_t)(b0 + b) * SS) * HH + hq * 8;
            float acm[8];
            #pragma unroll
            for (int q = 0; q < 8; ++q) {
                acm[q] = 0.f;
            }
            #pragma unroll 8
            for (int s_ = 0; s_ < SS; ++s_) {
                float w = scor_s[b * SS + s_];
                uint4 v = *(const uint4*)(ep + (size_t)s_ * HH);
                __half2* hp = (__half2*)&v;
                #pragma unroll
                for (int q = 0; q < 4; ++q) {
                    float2 f2 = __half22float2(hp[q]);
                    acm[2 * q]     += w * f2.x;
                    acm[2 * q + 1] += w * f2.y;
                }
            }
            #pragma unroll
            for (int q = 0; q < 8; ++q) {
                c_s[b * HSTR + hq * 8 + q] = acm[q];
            }
        }
        __syncthreads();

        float af[6][4];
        {
            unsigned long long acc2[6][2];
            #pragma unroll
            for (int gi = 0; gi < 6; ++gi) {
                float bb = bdec_s[gg + 64 * gi];
                acc2[gi][0] = pack2(bb, bb);
                acc2[gi][1] = pack2(bb, bb);
            }
            gemm_accum<6, 384>(Wih_d, c_s, acc2, wbuf, tid, gg, bg);
            gemm_accum<6, 384>(Whh_d, h_s, acc2, wbuf, tid, gg, bg);
            #pragma unroll
            for (int gi = 0; gi < 6; ++gi) {
                unpack2(acc2[gi][0], af[gi][0], af[gi][1]);
                unpack2(acc2[gi][1], af[gi][2], af[gi][3]);
            }
        }

        #pragma unroll
        for (int jj = 0; jj < 2; ++jj) {
            int j = gg + 64 * jj;
            #pragma unroll
            for (int bi = 0; bi < 4; ++bi) {
                int b = bg + 4 * bi;
                float iv = sigf(af[0 + jj][bi]);
                float fv = sigf(af[2 + jj][bi]);
                float gv = tanh_f(af[4 + jj][bi]);
                h_s[b * HSTR + j] = fv * h_s[b * HSTR + j] + iv * gv;
            }
        }
        __syncthreads();

        if (tid < BT * FF) {
            int b = tid / FF;
            int f = tid - b * FF;
            float a = 0.f;
            #pragma unroll
            for (int j4 = 0; j4 < 32; ++j4) {
                float4 cv = *(const float4*)(h_s + b * HSTR + j4 * 4);
                float4 wv = *(const float4*)(wout_s + f * HH + j4 * 4);
                a += cv.x * wv.x + cv.y * wv.y + cv.z * wv.z + cv.w * wv.w;
            }
            y_s[b * 8 + f] = a + bout_s[f];
        }
        __syncthreads();
        if (tid < BT) {
            float a = bfin_s[0];
            #pragma unroll
            for (int f = 0; f < FF; ++f) {
                a += y_s[tid * 8 + f] * wfin_s[f];
            }
            out[(size_t)(b0 + tid) * PP + p] = a;
        }
        __syncthreads();
    }
}

extern "C" void kernel_launch(void* const* d_in, const int* in_sizes, int n_in,
                              void* d_out, int out_size)
{
    (void)in_sizes; (void)n_in; (void)out_size;
    cudaFuncSetAttribute(edk_kernel, cudaFuncAttributeMaxDynamicSharedMemorySize, SMEM_BYTES);
    edk_kernel<<<NCTA, NTHR, SMEM_BYTES>>>(
        (const float*)d_in[0],  (const float*)d_in[1],  (const float*)d_in[2],
        (const float*)d_in[3],  (const float*)d_in[4],  (const float*)d_in[5],
        (const float*)d_in[6],  (const float*)d_in[7],  (const float*)d_in[8],
        (const float*)d_in[9],  (const float*)d_in[10], (const float*)d_in[11],
        (const float*)d_in[12], (const float*)d_in[13], (const float*)d_in[14],
        (float*)d_out);
}

// round 12
// speedup vs baseline: 2.4635x; 1.4348x over previous
#include <cuda_runtime.h>
#include <cuda_fp16.h>
#include <cstdint>
#include <cstddef>

#define BB   2048
#define SS   168
#define FF   7
#define HH   128
#define GG4  512
#define PP   96
#define AAT  135
#define BT   16
#define NCTA 128
#define NTHR 256
#define HSTR 136
#define WSTR 140

// smem float offsets
#define OFF_HS    0
#define OFF_CMB   2176              /* 16x136 fp16 combine = 1088 fl */
#define OFF_HD    3264              /* 16x136 fp16 h      = 1088 fl */
#define OFF_YS    4352
#define OFF_BDEC  4480
#define OFF_BATT  4992
#define OFF_WOUT  5168
#define OFF_MISC  6064
// union base @ 6144
#define OFF_STAGE 6144              /* enc: 512*17 fp32 */
#define OFF_HSM   14848             /* enc: 16*136 fp16 = 1088 fl */
#define OFF_WIH   15936             /* enc: 512*9 fp32 */
#define OFF_XBS   20544             /* enc: 16*1176 fp32 */
#define OFF_WATT  6144              /* dec: 168*140 fp32 */
#define OFF_SCOR  29664             /* dec: 16*168 fp32 */
#define SMEM_FLOATS 39360
#define SMEM_BYTES  (SMEM_FLOATS * 4)

static __device__ __half g_enc[(size_t)BB * SS * HH];

__device__ __forceinline__ float sigf(float x) { return __fdividef(1.f, 1.f + __expf(-x)); }
__device__ __forceinline__ float tanh_f(float x) {
    float ax = fabsf(x);
    float t  = __expf(-2.f * ax);
    return copysignf(__fdividef(1.f - t, 1.f + t), x);
}
__device__ __forceinline__ uint32_t f2h2(float lo, float hi) {
    __half2 h = __floats2half2_rn(lo, hi);
    return *reinterpret_cast<uint32_t*>(&h);
}
__device__ __forceinline__ void mma16816(float* c, const uint32_t* a, uint32_t b0, uint32_t b1) {
    asm volatile(
        "mma.sync.aligned.m16n8k16.row.col.f32.f16.f16.f32 "
        "{%0,%1,%2,%3}, {%4,%5,%6,%7}, {%8,%9}, {%0,%1,%2,%3};"
        : "+f"(c[0]), "+f"(c[1]), "+f"(c[2]), "+f"(c[3])
        : "r"(a[0]), "r"(a[1]), "r"(a[2]), "r"(a[3]), "r"(b0), "r"(b1));
}

extern "C" __global__ void __launch_bounds__(NTHR, 1)
edk_kernel(const float* __restrict__ xb,
           const float* __restrict__ Wih_e, const float* __restrict__ Whh_e,
           const float* __restrict__ bih_e, const float* __restrict__ bhh_e,
           const float* __restrict__ Watt,  const float* __restrict__ batt,
           const float* __restrict__ Wih_d, const float* __restrict__ Whh_d,
           const float* __restrict__ bih_d, const float* __restrict__ bhh_d,
           const float* __restrict__ Wout,  const float* __restrict__ bout,
           const float* __restrict__ Wfin,  const float* __restrict__ bfin,
           float* __restrict__ out)
{
    extern __shared__ float sm[];
    const int tid = threadIdx.x;
    const int wid = tid >> 5;
    const int lane = tid & 31;
    const int gid = lane >> 2;
    const int tig = lane & 3;
    const int b0 = blockIdx.x * BT;

    float* h_s    = sm + OFF_HS;
    __half* cmb16 = (__half*)(sm + OFF_CMB);
    __half* hd16  = (__half*)(sm + OFF_HD);
    float* y_s    = sm + OFF_YS;
    float* bdec_s = sm + OFF_BDEC;
    float* batt_s = sm + OFF_BATT;
    float* wout_s = sm + OFF_WOUT;
    float* wfin_s = sm + OFF_MISC;
    float* bout_s = sm + OFF_MISC + 8;
    float* bfin_s = sm + OFF_MISC + 16;
    float* stage  = sm + OFF_STAGE;
    __half* hsm   = (__half*)(sm + OFF_HSM);
    float* wih_s  = sm + OFF_WIH;
    float* xbs    = sm + OFF_XBS;

    // init loads
    for (int i = tid; i < BT * SS * FF; i += NTHR) {
        int b = i / (SS * FF);
        int r = i - b * (SS * FF);
        xbs[b * 1176 + r] = xb[(size_t)(b0 + b) * (SS * FF) + r];
    }
    for (int i = tid; i < GG4; i += NTHR) {
        #pragma unroll
        for (int f = 0; f < FF; ++f) {
            wih_s[i * 9 + f] = Wih_e[i * FF + f];
        }
        wih_s[i * 9 + 7] = bih_e[i] + bhh_e[i];
        bdec_s[i] = bih_d[i] + bhh_d[i];
    }
    for (int i = tid; i < 1088; i += NTHR) {
        ((float*)hsm)[i] = 0.f;
    }
    for (int i = tid; i < SS; i += NTHR) {
        batt_s[i] = batt[i];
    }
    for (int i = tid; i < FF * HH; i += NTHR) {
        wout_s[i] = Wout[i];
    }
    if (tid < FF) {
        wfin_s[tid] = Wfin[tid];
        bout_s[tid] = bout[tid];
    }
    if (tid == 0) {
        bfin_s[0] = bfin[0];
    }
    for (int i = tid; i < BT * 8; i += NTHR) {
        int b = i >> 3;
        int f = i & 7;
        y_s[i] = (f < FF) ? xb[(size_t)(b0 + b) * (SS * FF) + (SS - 1) * FF + f] : 0.f;
    }

    // fragment register file (encoder: 128 used; decoder: 192 used)
    uint32_t frg[192];

    // encoder A-frags: Whh_e fp16; warp owns rows [wid*64, wid*64+64)
    #pragma unroll
    for (int mt = 0; mt < 4; ++mt) {
        #pragma unroll
        for (int kt = 0; kt < 8; ++kt) {
            int r0 = wid * 64 + mt * 16 + gid;
            int c0 = kt * 16 + tig * 2;
            float2 v00 = *(const float2*)(Whh_e + (size_t)(r0    ) * HH + c0    );
            float2 v10 = *(const float2*)(Whh_e + (size_t)(r0 + 8) * HH + c0    );
            float2 v01 = *(const float2*)(Whh_e + (size_t)(r0    ) * HH + c0 + 8);
            float2 v11 = *(const float2*)(Whh_e + (size_t)(r0 + 8) * HH + c0 + 8);
            frg[(mt * 8 + kt) * 4 + 0] = f2h2(v00.x, v00.y);
            frg[(mt * 8 + kt) * 4 + 1] = f2h2(v10.x, v10.y);
            frg[(mt * 8 + kt) * 4 + 2] = f2h2(v01.x, v01.y);
            frg[(mt * 8 + kt) * 4 + 3] = f2h2(v11.x, v11.y);
        }
    }
    __syncthreads();

    // ---- encoder: 168 HMMA LSTM steps ----
    const int aj = tid >> 1;
    const int bh = (tid & 1) << 3;
    float creg[8];
    #pragma unroll
    for (int q = 0; q < 8; ++q) {
        creg[q] = 0.f;
    }

    for (int s = 0; s < SS; ++s) {
        float acc[4][2][4];
        #pragma unroll
        for (int mt = 0; mt < 4; ++mt) {
            #pragma unroll
            for (int nt = 0; nt < 2; ++nt) {
                #pragma unroll
                for (int q = 0; q < 4; ++q) {
                    acc[mt][nt][q] = 0.f;
                }
            }
        }
        #pragma unroll
        for (int kt = 0; kt < 8; ++kt) {
            int kb = kt * 16 + tig * 2;
            uint32_t bA0 = *(const uint32_t*)(hsm + (gid    ) * 136 + kb    );
            uint32_t bA1 = *(const uint32_t*)(hsm + (gid    ) * 136 + kb + 8);
            uint32_t bB0 = *(const uint32_t*)(hsm + (gid + 8) * 136 + kb    );
            uint32_t bB1 = *(const uint32_t*)(hsm + (gid + 8) * 136 + kb + 8);
            #pragma unroll
            for (int mt = 0; mt < 4; ++mt) {
                mma16816(acc[mt][0], frg + (mt * 8 + kt) * 4, bA0, bA1);
                mma16816(acc[mt][1], frg + (mt * 8 + kt) * 4, bB0, bB1);
            }
        }
        #pragma unroll
        for (int mt = 0; mt < 4; ++mt) {
            #pragma unroll
            for (int nt = 0; nt < 2; ++nt) {
                int g0 = wid * 64 + mt * 16 + gid;
                int bb = nt * 8 + tig * 2;
                stage[g0 * 17 + bb]           = acc[mt][nt][0];
                stage[g0 * 17 + bb + 1]       = acc[mt][nt][1];
                stage[(g0 + 8) * 17 + bb]     = acc[mt][nt][2];
                stage[(g0 + 8) * 17 + bb + 1] = acc[mt][nt][3];
            }
        }
        __syncthreads();

        #pragma unroll
        for (int bi = 0; bi < 8; ++bi) {
            int b = bh + bi;
            float xf[7];
            #pragma unroll
            for (int f = 0; f < FF; ++f) {
                xf[f] = xbs[b * 1176 + s * FF + f];
            }
            float pre[4];
            #pragma unroll
            for (int gt = 0; gt < 4; ++gt) {
                const float* wr = wih_s + (gt * 128 + aj) * 9;
                float a = wr[7];
                #pragma unroll
                for (int f = 0; f < FF; ++f) {
                    a += wr[f] * xf[f];
                }
                pre[gt] = a + stage[(gt * 128 + aj) * 17 + b];
            }
            float cc = sigf(pre[1]) * creg[bi] + sigf(pre[0]) * tanh_f(pre[2]);
            float hh = sigf(pre[3]) * tanh_f(cc);
            creg[bi] = cc;
            hsm[b * 136 + aj] = __float2half_rn(hh);
            g_enc[((size_t)(b0 + b) * SS + s) * HH + aj] = __float2half_rn(hh);
            if (s == SS - 1) {
                h_s[b * HSTR + aj] = hh;
            }
        }
        __syncthreads();
    }

    // ---- decoder setup ----
    float* watt_s = sm + OFF_WATT;
    float* scor_s = sm + OFF_SCOR;
    for (int i = tid; i < SS * WSTR; i += NTHR) {
        int s_ = i / WSTR;
        int a_ = i - s_ * WSTR;
        watt_s[i] = (a_ < AAT) ? Watt[s_ * AAT + a_] : 0.f;
    }
    for (int i = tid; i < BT * HH; i += NTHR) {
        int b = i >> 7;
        int j = i & 127;
        hd16[b * 136 + j] = __float2half_rn(h_s[b * HSTR + j]);
    }

    // decoder A-frags: [Wih_d | Whh_d] fp16, warp owns j in [wid*16, wid*16+16), gates i/f/g
    #pragma unroll
    for (int g = 0; g < 3; ++g) {
        #pragma unroll
        for (int kt = 0; kt < 16; ++kt) {
            const float* W = (kt < 8) ? Wih_d : Whh_d;
            int R = g * 128 + wid * 16 + gid;
            int c0 = (kt & 7) * 16 + tig * 2;
            float2 v00 = *(const float2*)(W + (size_t)(R    ) * HH + c0    );
            float2 v10 = *(const float2*)(W + (size_t)(R + 8) * HH + c0    );
            float2 v01 = *(const float2*)(W + (size_t)(R    ) * HH + c0 + 8);
            float2 v11 = *(const float2*)(W + (size_t)(R + 8) * HH + c0 + 8);
            frg[(g * 16 + kt) * 4 + 0] = f2h2(v00.x, v00.y);
            frg[(g * 16 + kt) * 4 + 1] = f2h2(v10.x, v10.y);
            frg[(g * 16 + kt) * 4 + 2] = f2h2(v01.x, v01.y);
            frg[(g * 16 + kt) * 4 + 3] = f2h2(v11.x, v11.y);
        }
    }
    __syncthreads();

    // ---- decoder: 96 steps ----
    for (int p = 0; p < PP; ++p) {
        // 1) scores = [prev_h | y_prev] @ W_att^T + b_att
        {
            int b = tid >> 4;
            int ts = tid & 15;
            float acs[11];
            #pragma unroll
            for (int si = 0; si < 11; ++si) {
                acs[si] = 0.f;
            }
            #pragma unroll 2
            for (int a4 = 0; a4 < 34; ++a4) {
                float4 av;
                if (a4 < 32) {
                    av = *(const float4*)(h_s + b * HSTR + a4 * 4);
                } else {
                    av = *(const float4*)(y_s + b * 8 + (a4 - 32) * 4);
                }
                #pragma unroll
                for (int si = 0; si < 11; ++si) {
                    int s_ = ts + 16 * si;
                    if (s_ < SS) {
                        float4 wv = *(const float4*)(watt_s + s_ * WSTR + a4 * 4);
                        acs[si] += av.x * wv.x + av.y * wv.y + av.z * wv.z + av.w * wv.w;
                    }
                }
            }
            #pragma unroll
            for (int si = 0; si < 11; ++si) {
                int s_ = ts + 16 * si;
                if (s_ < SS) {
                    scor_s[b * SS + s_] = acs[si] + batt_s[s_];
                }
            }
        }
        __syncthreads();

        // 2) softmax
        {
            int b = 2 * wid + (lane >> 4);
            int l16 = lane & 15;
            float mx = -1e30f;
            for (int s_ = l16; s_ < SS; s_ += 16) {
                mx = fmaxf(mx, scor_s[b * SS + s_]);
            }
            #pragma unroll
            for (int o = 8; o >= 1; o >>= 1) {
                mx = fmaxf(mx, __shfl_xor_sync(0xffffffffu, mx, o));
            }
            float sum = 0.f;
            for (int s_ = l16; s_ < SS; s_ += 16) {
                float e = __expf(scor_s[b * SS + s_] - mx);
                scor_s[b * SS + s_] = e;
                sum += e;
            }
            #pragma unroll
            for (int o = 8; o >= 1; o >>= 1) {
                sum += __shfl_xor_sync(0xffffffffu, sum, o);
            }
            float inv = __fdividef(1.f, sum);
            for (int s_ = l16; s_ < SS; s_ += 16) {
                scor_s[b * SS + s_] *= inv;
            }
        }
        __syncthreads();

        // 3) combine = attn_w @ enc_out (fp16 L2 reads) -> cmb16
        {
            int b = tid >> 4;
            int hq = tid & 15;
            const __half* ep = g_enc + ((size_t)(b0 + b) * SS) * HH + hq * 8;
            float acm[8];
            #pragma unroll
            for (int q = 0; q < 8; ++q) {
                acm[q] = 0.f;
            }
            #pragma unroll 8
            for (int s_ = 0; s_ < SS; ++s_) {
                float w = scor_s[b * SS + s_];
                uint4 v = *(const uint4*)(ep + (size_t)s_ * HH);
                __half2* hp = (__half2*)&v;
                #pragma unroll
                for (int q = 0; q < 4; ++q) {
                    float2 f2 = __half22float2(hp[q]);
                    acm[2 * q]     += w * f2.x;
                    acm[2 * q + 1] += w * f2.y;
                }
            }
            #pragma unroll
            for (int q = 0; q < 4; ++q) {
                *(__half2*)(cmb16 + b * 136 + hq * 8 + 2 * q) =
                    __floats2half2_rn(acm[2 * q], acm[2 * q + 1]);
            }
        }
        __syncthreads();

        // 4) gates via HMMA: [384x16x256] over [combine | prev_h]
        {
            float acc[3][2][4];
            #pragma unroll
            for (int g = 0; g < 3; ++g) {
                #pragma unroll
                for (int nt = 0; nt < 2; ++nt) {
                    #pragma unroll
                    for (int q = 0; q < 4; ++q) {
                        acc[g][nt][q] = 0.f;
                    }
                }
            }
            #pragma unroll
            for (int kt = 0; kt < 16; ++kt) {
                const __half* src = (kt < 8) ? cmb16 : hd16;
                int kb = (kt & 7) * 16 + tig * 2;
                uint32_t bA0 = *(const uint32_t*)(src + (gid    ) * 136 + kb    );
                uint32_t bA1 = *(const uint32_t*)(src + (gid    ) * 136 + kb + 8);
                uint32_t bB0 = *(const uint32_t*)(src + (gid + 8) * 136 + kb    );
                uint32_t bB1 = *(const uint32_t*)(src + (gid + 8) * 136 + kb + 8);
                #pragma unroll
                for (int g = 0; g < 3; ++g) {
                    mma16816(acc[g][0], frg + (g * 16 + kt) * 4, bA0, bA1);
                    mma16816(acc[g][1], frg + (g * 16 + kt) * 4, bB0, bB1);
                }
            }
            __syncthreads();
            // epilogue: c_new = sig(f)*prev_h + sig(i)*tanh(g)
            #pragma unroll
            for (int nt = 0; nt < 2; ++nt) {
                #pragma unroll
                for (int q = 0; q < 4; ++q) {
                    int j = wid * 16 + gid + ((q >> 1) << 3);
                    int b = nt * 8 + tig * 2 + (q & 1);
                    float pi = acc[0][nt][q] + bdec_s[j];
                    float pf = acc[1][nt][q] + bdec_s[128 + j];
                    float pg = acc[2][nt][q] + bdec_s[256 + j];
                    float ph = h_s[b * HSTR + j];
                    float cn = sigf(pf) * ph + sigf(pi) * tanh_f(pg);
                    h_s[b * HSTR + j] = cn;
                    hd16[b * 136 + j] = __float2half_rn(cn);
                }
            }
        }
        __syncthreads();

        // 5) out = c_new @ W_out^T + b_out; final = out @ W_fin + b_fin
        if (tid < BT * FF) {
            int b = tid / FF;
            int f = tid - b * FF;
            float a = 0.f;
            #pragma unroll
            for (int j4 = 0; j4 < 32; ++j4) {
                float4 cv = *(const float4*)(h_s + b * HSTR + j4 * 4);
                float4 wv = *(const float4*)(wout_s + f * HH + j4 * 4);
                a += cv.x * wv.x + cv.y * wv.y + cv.z * wv.z + cv.w * wv.w;
            }
            y_s[b * 8 + f] = a + bout_s[f];
        }
        __syncthreads();
        if (tid < BT) {
            float a = bfin_s[0];
            #pragma unroll
            for (int f = 0; f < FF; ++f) {
                a += y_s[tid * 8 + f] * wfin_s[f];
            }
            out[(size_t)(b0 + tid) * PP + p] = a;
        }
        __syncthreads();
    }
}

extern "C" void kernel_launch(void* const* d_in, const int* in_sizes, int n_in,
                              void* d_out, int out_size)
{
    (void)in_sizes; (void)n_in; (void)out_size;
    cudaFuncSetAttribute(edk_kernel, cudaFuncAttributeMaxDynamicSharedMemorySize, SMEM_BYTES);
    edk_kernel<<<NCTA, NTHR, SMEM_BYTES>>>(
        (const float*)d_in[0],  (const float*)d_in[1],  (const float*)d_in[2],
        (const float*)d_in[3],  (const float*)d_in[4],  (const float*)d_in[5],
        (const float*)d_in[6],  (const float*)d_in[7],  (const float*)d_in[8],
        (const float*)d_in[9],  (const float*)d_in[10], (const float*)d_in[11],
        (const float*)d_in[12], (const float*)d_in[13], (const float*)d_in[14],
        (float*)d_out);
}

// round 13
// speedup vs baseline: 3.3321x; 1.3526x over previous
#include <cuda_runtime.h>
#include <cuda_fp16.h>
#include <cstdint>
#include <cstddef>

#define BB   2048
#define SS   168
#define FF   7
#define HH   128
#define GG4  512
#define PP   96
#define AAT  135
#define BT   16
#define NCTA 128
#define NTHR 256
#define HSTR 136
#define ASTR 152    /* fp16 row stride for attin/cmb/watt tiles */

// smem float offsets
#define OFF_HS    0                 /* 16x136 fp32 c-carry */
#define OFF_ATTIN 2176              /* 16x152 fp16 [h|y|0] */
#define OFF_CMB   3392              /* 16x152 fp16 combine */
#define OFF_WS    4608              /* 16x176 fp16 softmax w */
#define OFF_YS    6016              /* 16x8 fp32 */
#define OFF_BDEC  6144              /* 512 */
#define OFF_BATT  6656              /* 176 */
#define OFF_WOUT  6832              /* 7x128 */
#define OFF_MISC  7728
// union @ 7760
#define OFF_STAGE 7760              /* enc: 512*17 fp32 */
#define OFF_HSM   16464             /* enc: 16*136 fp16 */
#define OFF_WIH   17552             /* enc: 512*9 fp32 */
#define OFF_XBS   22160             /* enc: 16*1176 fp32 */
#define OFF_WATT  7760              /* dec: 176*152 fp16 */
#define OFF_SCOR  21136             /* dec: 16*168 fp32 */
#define SMEM_FLOATS 40976
#define SMEM_BYTES  (SMEM_FLOATS * 4)

// encoder output, pre-fragmented mma A layout: [b][kt(11)][mt(8)][lane(32)][reg(4) as 8 halves]
static __device__ __half g_encf[(size_t)BB * 88 * 256];

__device__ __forceinline__ float sigf(float x) { return __fdividef(1.f, 1.f + __expf(-x)); }
__device__ __forceinline__ float tanh_f(float x) {
    float ax = fabsf(x);
    float t  = __expf(-2.f * ax);
    return copysignf(__fdividef(1.f - t, 1.f + t), x);
}
__device__ __forceinline__ uint32_t f2h2(float lo, float hi) {
    __half2 h = __floats2half2_rn(lo, hi);
    return *reinterpret_cast<uint32_t*>(&h);
}
__device__ __forceinline__ void mma16816(float* c, const uint32_t* a, uint32_t b0, uint32_t b1) {
    asm volatile(
        "mma.sync.aligned.m16n8k16.row.col.f32.f16.f16.f32 "
        "{%0,%1,%2,%3}, {%4,%5,%6,%7}, {%8,%9}, {%0,%1,%2,%3};"
        : "+f"(c[0]), "+f"(c[1]), "+f"(c[2]), "+f"(c[3])
        : "r"(a[0]), "r"(a[1]), "r"(a[2]), "r"(a[3]), "r"(b0), "r"(b1));
}

extern "C" __global__ void __launch_bounds__(NTHR, 1)
edk_kernel(const float* __restrict__ xb,
           const float* __restrict__ Wih_e, const float* __restrict__ Whh_e,
           const float* __restrict__ bih_e, const float* __restrict__ bhh_e,
           const float* __restrict__ Watt,  const float* __restrict__ batt,
           const float* __restrict__ Wih_d, const float* __restrict__ Whh_d,
           const float* __restrict__ bih_d, const float* __restrict__ bhh_d,
           const float* __restrict__ Wout,  const float* __restrict__ bout,
           const float* __restrict__ Wfin,  const float* __restrict__ bfin,
           float* __restrict__ out)
{
    extern __shared__ float sm[];
    const int tid = threadIdx.x;
    const int wid = tid >> 5;
    const int lane = tid & 31;
    const int gid = lane >> 2;
    const int tig = lane & 3;
    const int b0 = blockIdx.x * BT;

    float* h_s     = sm + OFF_HS;
    __half* attin16 = (__half*)(sm + OFF_ATTIN);
    __half* cmb16  = (__half*)(sm + OFF_CMB);
    __half* ws16   = (__half*)(sm + OFF_WS);
    float* y_s     = sm + OFF_YS;
    float* bdec_s  = sm + OFF_BDEC;
    float* batt_s  = sm + OFF_BATT;
    float* wout_s  = sm + OFF_WOUT;
    float* wfin_s  = sm + OFF_MISC;
    float* bout_s  = sm + OFF_MISC + 8;
    float* bfin_s  = sm + OFF_MISC + 16;
    float* stage   = sm + OFF_STAGE;
    __half* hsm    = (__half*)(sm + OFF_HSM);
    float* wih_s   = sm + OFF_WIH;
    float* xbs     = sm + OFF_XBS;

    // init loads
    for (int i = tid; i < BT * SS * FF; i += NTHR) {
        int b = i / (SS * FF);
        int r = i - b * (SS * FF);
        xbs[b * 1176 + r] = xb[(size_t)(b0 + b) * (SS * FF) + r];
    }
    for (int i = tid; i < GG4; i += NTHR) {
        #pragma unroll
        for (int f = 0; f < FF; ++f) {
            wih_s[i * 9 + f] = Wih_e[i * FF + f];
        }
        wih_s[i * 9 + 7] = bih_e[i] + bhh_e[i];
        bdec_s[i] = bih_d[i] + bhh_d[i];
    }
    for (int i = tid; i < 1088; i += NTHR) {
        ((float*)hsm)[i] = 0.f;
    }
    for (int i = tid; i < SS; i += NTHR) {
        batt_s[i] = batt[i];
    }
    for (int i = tid; i < FF * HH; i += NTHR) {
        wout_s[i] = Wout[i];
    }
    if (tid < FF) {
        wfin_s[tid] = Wfin[tid];
        bout_s[tid] = bout[tid];
    }
    if (tid == 0) {
        bfin_s[0] = bfin[0];
    }
    for (int i = tid; i < BT * 8; i += NTHR) {
        int b = i >> 3;
        int f = i & 7;
        y_s[i] = (f < FF) ? xb[(size_t)(b0 + b) * (SS * FF) + (SS - 1) * FF + f] : 0.f;
    }

    // fragment register file (encoder: 128 used; decoder: 192 used)
    uint32_t frg[192];

    // encoder A-frags: Whh_e fp16; warp owns rows [wid*64, wid*64+64)
    #pragma unroll
    for (int mt = 0; mt < 4; ++mt) {
        #pragma unroll
        for (int kt = 0; kt < 8; ++kt) {
            int r0 = wid * 64 + mt * 16 + gid;
            int c0 = kt * 16 + tig * 2;
            float2 v00 = *(const float2*)(Whh_e + (size_t)(r0    ) * HH + c0    );
            float2 v10 = *(const float2*)(Whh_e + (size_t)(r0 + 8) * HH + c0    );
            float2 v01 = *(const float2*)(Whh_e + (size_t)(r0    ) * HH + c0 + 8);
            float2 v11 = *(const float2*)(Whh_e + (size_t)(r0 + 8) * HH + c0 + 8);
            frg[(mt * 8 + kt) * 4 + 0] = f2h2(v00.x, v00.y);
            frg[(mt * 8 + kt) * 4 + 1] = f2h2(v10.x, v10.y);
            frg[(mt * 8 + kt) * 4 + 2] = f2h2(v01.x, v01.y);
            frg[(mt * 8 + kt) * 4 + 3] = f2h2(v11.x, v11.y);
        }
    }
    __syncthreads();

    // ---- encoder: 168 HMMA LSTM steps ----
    const int aj = tid >> 1;
    const int bh = (tid & 1) << 3;
    // g_encf write coords (fixed per thread)
    const int mtW = aj >> 4;
    const int gidW = aj & 7;
    const int hi8W = (aj >> 3) & 1;
    float creg[8];
    #pragma unroll
    for (int q = 0; q < 8; ++q) {
        creg[q] = 0.f;
    }

    for (int s = 0; s < SS; ++s) {
        float acc[4][2][4];
        #pragma unroll
        for (int mt = 0; mt < 4; ++mt) {
            #pragma unroll
            for (int nt = 0; nt < 2; ++nt) {
                #pragma unroll
                for (int q = 0; q < 4; ++q) {
                    acc[mt][nt][q] = 0.f;
                }
            }
        }
        #pragma unroll
        for (int kt = 0; kt < 8; ++kt) {
            int kb = kt * 16 + tig * 2;
            uint32_t bA0 = *(const uint32_t*)(hsm + (gid    ) * 136 + kb    );
            uint32_t bA1 = *(const uint32_t*)(hsm + (gid    ) * 136 + kb + 8);
            uint32_t bB0 = *(const uint32_t*)(hsm + (gid + 8) * 136 + kb    );
            uint32_t bB1 = *(const uint32_t*)(hsm + (gid + 8) * 136 + kb + 8);
            #pragma unroll
            for (int mt = 0; mt < 4; ++mt) {
                mma16816(acc[mt][0], frg + (mt * 8 + kt) * 4, bA0, bA1);
                mma16816(acc[mt][1], frg + (mt * 8 + kt) * 4, bB0, bB1);
            }
        }
        #pragma unroll
        for (int mt = 0; mt < 4; ++mt) {
            #pragma unroll
            for (int nt = 0; nt < 2; ++nt) {
                int g0 = wid * 64 + mt * 16 + gid;
                int bb = nt * 8 + tig * 2;
                stage[g0 * 17 + bb]           = acc[mt][nt][0];
                stage[g0 * 17 + bb + 1]       = acc[mt][nt][1];
                stage[(g0 + 8) * 17 + bb]     = acc[mt][nt][2];
                stage[(g0 + 8) * 17 + bb + 1] = acc[mt][nt][3];
            }
        }
        __syncthreads();

        // fragment-store coords for this s
        const int ktS = s >> 4;
        const int cS = s & 15;
        const int tigW = (cS >> 1) & 3;
        const int regW = (cS >> 3) * 2 + hi8W;
        const int laneW = gidW * 4 + tigW;
        const int innerW = ((ktS * 8 + mtW) * 32 + laneW) * 8 + regW * 2 + (cS & 1);

        #pragma unroll
        for (int bi = 0; bi < 8; ++bi) {
            int b = bh + bi;
            float xf[7];
            #pragma unroll
            for (int f = 0; f < FF; ++f) {
                xf[f] = xbs[b * 1176 + s * FF + f];
            }
            float pre[4];
            #pragma unroll
            for (int gt = 0; gt < 4; ++gt) {
                const float* wr = wih_s + (gt * 128 + aj) * 9;
                float a = wr[7];
                #pragma unroll
                for (int f = 0; f < FF; ++f) {
                    a += wr[f] * xf[f];
                }
                pre[gt] = a + stage[(gt * 128 + aj) * 17 + b];
            }
            float cc = sigf(pre[1]) * creg[bi] + sigf(pre[0]) * tanh_f(pre[2]);
            float hh = sigf(pre[3]) * tanh_f(cc);
            creg[bi] = cc;
            hsm[b * 136 + aj] = __float2half_rn(hh);
            g_encf[(size_t)(b0 + b) * 22528 + innerW] = __float2half_rn(hh);
            if (s == SS - 1) {
                h_s[b * HSTR + aj] = hh;
            }
        }
        __syncthreads();
    }

    // ---- decoder setup ----
    __half* watt16 = (__half*)(sm + OFF_WATT);
    float* scor_s  = sm + OFF_SCOR;
    // W_att fp16 tile [176][152], zero-padded
    for (int i = tid; i < 176 * 76; i += NTHR) {
        int r = i / 76;
        int c = (i - r * 76) * 2;
        float v0 = (r < SS && c < AAT) ? Watt[r * AAT + c] : 0.f;
        float v1 = (r < SS && c + 1 < AAT) ? Watt[r * AAT + c + 1] : 0.f;
        *(__half2*)(watt16 + r * ASTR + c) = __floats2half2_rn(v0, v1);
    }
    // attn_in tile [h | y | 0]
    for (int i = tid; i < BT * ASTR; i += NTHR) {
        int b = i / ASTR;
        int c = i - b * ASTR;
        float v = 0.f;
        if (c < HH) {
            v = h_s[b * HSTR + c];
        } else if (c < AAT) {
            v = y_s[b * 8 + (c - HH)];
        }
        attin16[i] = __float2half_rn(v);
    }
    // softmax-weight tile zero (pad rows 168..175 stay 0 forever)
    for (int i = tid; i < BT * 176; i += NTHR) {
        ws16[i] = __float2half_rn(0.f);
    }

    // decoder A-frags: [Wih_d | Whh_d] fp16, warp owns j in [wid*16, wid*16+16), gates i/f/g
    #pragma unroll
    for (int g = 0; g < 3; ++g) {
        #pragma unroll
        for (int kt = 0; kt < 16; ++kt) {
            const float* W = (kt < 8) ? Wih_d : Whh_d;
            int R = g * 128 + wid * 16 + gid;
            int c0 = (kt & 7) * 16 + tig * 2;
            float2 v00 = *(const float2*)(W + (size_t)(R    ) * HH + c0    );
            float2 v10 = *(const float2*)(W + (size_t)(R + 8) * HH + c0    );
            float2 v01 = *(const float2*)(W + (size_t)(R    ) * HH + c0 + 8);
            float2 v11 = *(const float2*)(W + (size_t)(R + 8) * HH + c0 + 8);
            frg[(g * 16 + kt) * 4 + 0] = f2h2(v00.x, v00.y);
            frg[(g * 16 + kt) * 4 + 1] = f2h2(v10.x, v10.y);
            frg[(g * 16 + kt) * 4 + 2] = f2h2(v01.x, v01.y);
            frg[(g * 16 + kt) * 4 + 3] = f2h2(v11.x, v11.y);
        }
    }
    __syncthreads();

    // ---- decoder: 96 steps ----
    for (int p = 0; p < PP; ++p) {
        // 1) scores via HMMA: W_att(176x144) @ attn_in^T -> scor_s[b][s]
        {
            float sA[4] = {0.f, 0.f, 0.f, 0.f};
            float sB[4] = {0.f, 0.f, 0.f, 0.f};
            float sC[4] = {0.f, 0.f, 0.f, 0.f};
            float sD[4] = {0.f, 0.f, 0.f, 0.f};
            const int mt0 = wid;
            const int mt1 = 8 + wid;
            #pragma unroll
            for (int kt = 0; kt < 9; ++kt) {
                int kb = kt * 16 + tig * 2;
                uint32_t bA0 = *(const uint32_t*)(attin16 + (gid    ) * ASTR + kb    );
                uint32_t bA1 = *(const uint32_t*)(attin16 + (gid    ) * ASTR + kb + 8);
                uint32_t bB0 = *(const uint32_t*)(attin16 + (gid + 8) * ASTR + kb    );
                uint32_t bB1 = *(const uint32_t*)(attin16 + (gid + 8) * ASTR + kb + 8);
                uint32_t a[4];
                a[0] = *(const uint32_t*)(watt16 + (mt0 * 16 + gid    ) * ASTR + kb    );
                a[1] = *(const uint32_t*)(watt16 + (mt0 * 16 + 8 + gid) * ASTR + kb    );
                a[2] = *(const uint32_t*)(watt16 + (mt0 * 16 + gid    ) * ASTR + kb + 8);
                a[3] = *(const uint32_t*)(watt16 + (mt0 * 16 + 8 + gid) * ASTR + kb + 8);
                mma16816(sA, a, bA0, bA1);
                mma16816(sB, a, bB0, bB1);
                if (wid < 3) {
                    a[0] = *(const uint32_t*)(watt16 + (mt1 * 16 + gid    ) * ASTR + kb    );
                    a[1] = *(const uint32_t*)(watt16 + (mt1 * 16 + 8 + gid) * ASTR + kb    );
                    a[2] = *(const uint32_t*)(watt16 + (mt1 * 16 + gid    ) * ASTR + kb + 8);
                    a[3] = *(const uint32_t*)(watt16 + (mt1 * 16 + 8 + gid) * ASTR + kb + 8);
                    mma16816(sC, a, bA0, bA1);
                    mma16816(sD, a, bB0, bB1);
                }
            }
            #pragma unroll
            for (int q = 0; q < 4; ++q) {
                int si = mt0 * 16 + gid + ((q >> 1) << 3);
                int bb = tig * 2 + (q & 1);
                scor_s[bb * SS + si] = sA[q] + batt_s[si];
                scor_s[(bb + 8) * SS + si] = sB[q] + batt_s[si];
                if (wid < 3) {
                    int sj = mt1 * 16 + gid + ((q >> 1) << 3);
                    if (sj < SS) {
                        scor_s[bb * SS + sj] = sC[q] + batt_s[sj];
                        scor_s[(bb + 8) * SS + sj] = sD[q] + batt_s[sj];
                    }
                }
            }
        }
        __syncthreads();

        // 2) softmax -> scor_s (fp32) and ws16 (fp16)
        {
            int b = 2 * wid + (lane >> 4);
            int l16 = lane & 15;
            float mx = -1e30f;
            for (int s_ = l16; s_ < SS; s_ += 16) {
                mx = fmaxf(mx, scor_s[b * SS + s_]);
            }
            #pragma unroll
            for (int o = 8; o >= 1; o >>= 1) {
                mx = fmaxf(mx, __shfl_xor_sync(0xffffffffu, mx, o));
            }
            float sum = 0.f;
            for (int s_ = l16; s_ < SS; s_ += 16) {
                float e = __expf(scor_s[b * SS + s_] - mx);
                scor_s[b * SS + s_] = e;
                sum += e;
            }
            #pragma unroll
            for (int o = 8; o >= 1; o >>= 1) {
                sum += __shfl_xor_sync(0xffffffffu, sum, o);
            }
            float inv = __fdividef(1.f, sum);
            for (int s_ = l16; s_ < SS; s_ += 16) {
                float w = scor_s[b * SS + s_] * inv;
                ws16[b * 176 + s_] = __float2half_rn(w);
            }
        }
        __syncthreads();

        // 3) combine via HMMA on pre-fragmented enc tiles: warp does 2 batches
        {
            #pragma unroll
            for (int bi = 0; bi < 2; ++bi) {
                int b = wid * 2 + bi;
                const uint4* ap = (const uint4*)g_encf + ((size_t)(b0 + b) * 88) * 32 + lane;
                const __half* wp = ws16 + b * 176;
                #pragma unroll
                for (int hm = 0; hm < 2; ++hm) {
                    float cc[4][4];
                    #pragma unroll
                    for (int m = 0; m < 4; ++m) {
                        #pragma unroll
                        for (int q = 0; q < 4; ++q) {
                            cc[m][q] = 0.f;
                        }
                    }
                    #pragma unroll
                    for (int kt = 0; kt < 11; ++kt) {
                        uint32_t wb0 = *(const uint32_t*)(wp + kt * 16 + tig * 2    );
                        uint32_t wb1 = *(const uint32_t*)(wp + kt * 16 + 8 + tig * 2);
                        #pragma unroll
                        for (int m = 0; m < 4; ++m) {
                            uint4 av = ap[(size_t)(kt * 8 + hm * 4 + m) * 32];
                            mma16816(cc[m], (const uint32_t*)&av, wb0, wb1);
                        }
                    }
                    if (tig == 0) {
                        #pragma unroll
                        for (int m = 0; m < 4; ++m) {
                            int h = (hm * 4 + m) * 16 + gid;
                            cmb16[b * ASTR + h]     = __float2half_rn(cc[m][0]);
                            cmb16[b * ASTR + h + 8] = __float2half_rn(cc[m][2]);
                        }
                    }
                }
            }
        }
        __syncthreads();

        // 4) gates via HMMA: [384x16x256] over [combine | prev_h]
        {
            float acc[3][2][4];
            #pragma unroll
            for (int g = 0; g < 3; ++g) {
                #pragma unroll
                for (int nt = 0; nt < 2; ++nt) {
                    #pragma unroll
                    for (int q = 0; q < 4; ++q) {
                        acc[g][nt][q] = 0.f;
                    }
                }
            }
            #pragma unroll
            for (int kt = 0; kt < 16; ++kt) {
                const __half* src = (kt < 8) ? cmb16 : attin16;
                int kb = (kt & 7) * 16 + tig * 2;
                uint32_t bA0 = *(const uint32_t*)(src + (gid    ) * ASTR + kb    );
                uint32_t bA1 = *(const uint32_t*)(src + (gid    ) * ASTR + kb + 8);
                uint32_t bB0 = *(const uint32_t*)(src + (gid + 8) * ASTR + kb    );
                uint32_t bB1 = *(const uint32_t*)(src + (gid + 8) * ASTR + kb + 8);
                #pragma unroll
                for (int g = 0; g < 3; ++g) {
                    mma16816(acc[g][0], frg + (g * 16 + kt) * 4, bA0, bA1);
                    mma16816(acc[g][1], frg + (g * 16 + kt) * 4, bB0, bB1);
                }
            }
            __syncthreads();
            // epilogue: c_new = sig(f)*prev_h + sig(i)*tanh(g)
            #pragma unroll
            for (int nt = 0; nt < 2; ++nt) {
                #pragma unroll
                for (int q = 0; q < 4; ++q) {
                    int j = wid * 16 + gid + ((q >> 1) << 3);
                    int b = nt * 8 + tig * 2 + (q & 1);
                    float pi = acc[0][nt][q] + bdec_s[j];
                    float pf = acc[1][nt][q] + bdec_s[128 + j];
                    float pg = acc[2][nt][q] + bdec_s[256 + j];
                    float ph = h_s[b * HSTR + j];
                    float cn = sigf(pf) * ph + sigf(pi) * tanh_f(pg);
                    h_s[b * HSTR + j] = cn;
                    attin16[b * ASTR + j] = __float2half_rn(cn);
                }
            }
        }
        __syncthreads();

        // 5) out = c_new @ W_out^T + b_out; y -> attin16; final = out @ W_fin + b_fin
        if (tid < BT * FF) {
            int b = tid / FF;
            int f = tid - b * FF;
            float a = 0.f;
            #pragma unroll
            for (int j4 = 0; j4 < 32; ++j4) {
                float4 cv = *(const float4*)(h_s + b * HSTR + j4 * 4);
                float4 wv = *(const float4*)(wout_s + f * HH + j4 * 4);
                a += cv.x * wv.x + cv.y * wv.y + cv.z * wv.z + cv.w * wv.w;
            }
            float y = a + bout_s[f];
            y_s[b * 8 + f] = y;
            attin16[b * ASTR + HH + f] = __float2half_rn(y);
        }
        __syncthreads();
        if (tid < BT) {
            float a = bfin_s[0];
            #pragma unroll
            for (int f = 0; f < FF; ++f) {
                a += y_s[tid * 8 + f] * wfin_s[f];
            }
            out[(size_t)(b0 + tid) * PP + p] = a;
        }
        __syncthreads();
    }
}

extern "C" void kernel_launch(void* const* d_in, const int* in_sizes, int n_in,
                              void* d_out, int out_size)
{
    (void)in_sizes; (void)n_in; (void)out_size;
    cudaFuncSetAttribute(edk_kernel, cudaFuncAttributeMaxDynamicSharedMemorySize, SMEM_BYTES);
    edk_kernel<<<NCTA, NTHR, SMEM_BYTES>>>(
        (const float*)d_in[0],  (const float*)d_in[1],  (const float*)d_in[2],
        (const float*)d_in[3],  (const float*)d_in[4],  (const float*)d_in[5],
        (const float*)d_in[6],  (const float*)d_in[7],  (const float*)d_in[8],
        (const float*)d_in[9],  (const float*)d_in[10], (const float*)d_in[11],
        (const float*)d_in[12], (const float*)d_in[13], (const float*)d_in[14],
        (float*)d_out);
}

// round 14
// speedup vs baseline: 4.7878x; 1.4369x over previous
#include <cuda_runtime.h>
#include <cuda_fp16.h>
#include <cstdint>
#include <cstddef>

#define BB   2048
#define SS   168
#define FF   7
#define HH   128
#define GG4  512
#define PP   96
#define AAT  135
#define BT   16
#define NCTA 128
#define NTHR 256
#define HSTR 136
#define ASTR 152    /* fp16 row stride for attin/cmb/watt tiles */

// smem float offsets
#define OFF_HS    0                 /* 16x136 fp32 c-carry */
#define OFF_ATTIN 2176              /* 16x152 fp16 [h|y|0] */
#define OFF_CMB   3392              /* 16x152 fp16 combine */
#define OFF_WS    4608              /* 16x176 fp16 softmax w */
#define OFF_YS    6016              /* 16x8 fp32 */
#define OFF_BDEC  6144              /* 512 */
#define OFF_BATT  6656              /* 176 */
#define OFF_WOUT  6832              /* 7x128 */
#define OFF_MISC  7728
// union @ 7760
#define OFF_STAGE 7760              /* enc: 512*17 fp32 */
#define OFF_HSM   16464             /* enc: 16*136 fp16 */
#define OFF_WIH   17552             /* enc: 512*9 fp32 */
#define OFF_XBS   22160             /* enc: 16*1176 fp32 */
#define OFF_WATT  7760              /* dec: 176*152 fp16 */
#define OFF_SCOR  21136             /* dec: 16*168 fp32 */
#define OFF_WDG   23824             /* dec: 128*264 fp16 g-gate weights */
#define SMEM_FLOATS 40976
#define SMEM_BYTES  (SMEM_FLOATS * 4)

// encoder output, pre-fragmented mma A layout: [b][kt(11)][mt(8)][lane(32)][reg(4) as 8 halves]
static __device__ __half g_encf[(size_t)BB * 88 * 256];

__device__ __forceinline__ float sigf(float x) { return __fdividef(1.f, 1.f + __expf(-x)); }
__device__ __forceinline__ float tanh_f(float x) {
    float ax = fabsf(x);
    float t  = __expf(-2.f * ax);
    return copysignf(__fdividef(1.f - t, 1.f + t), x);
}
__device__ __forceinline__ uint32_t f2h2(float lo, float hi) {
    __half2 h = __floats2half2_rn(lo, hi);
    return *reinterpret_cast<uint32_t*>(&h);
}
__device__ __forceinline__ void mma16816(float* c, const uint32_t* a, uint32_t b0, uint32_t b1) {
    asm volatile(
        "mma.sync.aligned.m16n8k16.row.col.f32.f16.f16.f32 "
        "{%0,%1,%2,%3}, {%4,%5,%6,%7}, {%8,%9}, {%0,%1,%2,%3};"
        : "+f"(c[0]), "+f"(c[1]), "+f"(c[2]), "+f"(c[3])
        : "r"(a[0]), "r"(a[1]), "r"(a[2]), "r"(a[3]), "r"(b0), "r"(b1));
}

extern "C" __global__ void __launch_bounds__(NTHR, 1)
edk_kernel(const float* __restrict__ xb,
           const float* __restrict__ Wih_e, const float* __restrict__ Whh_e,
           const float* __restrict__ bih_e, const float* __restrict__ bhh_e,
           const float* __restrict__ Watt,  const float* __restrict__ batt,
           const float* __restrict__ Wih_d, const float* __restrict__ Whh_d,
           const float* __restrict__ bih_d, const float* __restrict__ bhh_d,
           const float* __restrict__ Wout,  const float* __restrict__ bout,
           const float* __restrict__ Wfin,  const float* __restrict__ bfin,
           float* __restrict__ out)
{
    extern __shared__ float sm[];
    const int tid = threadIdx.x;
    const int wid = tid >> 5;
    const int lane = tid & 31;
    const int gid = lane >> 2;
    const int tig = lane & 3;
    const int b0 = blockIdx.x * BT;

    float* h_s     = sm + OFF_HS;
    __half* attin16 = (__half*)(sm + OFF_ATTIN);
    __half* cmb16  = (__half*)(sm + OFF_CMB);
    __half* ws16   = (__half*)(sm + OFF_WS);
    float* y_s     = sm + OFF_YS;
    float* bdec_s  = sm + OFF_BDEC;
    float* batt_s  = sm + OFF_BATT;
    float* wout_s  = sm + OFF_WOUT;
    float* wfin_s  = sm + OFF_MISC;
    float* bout_s  = sm + OFF_MISC + 8;
    float* bfin_s  = sm + OFF_MISC + 16;
    float* stage   = sm + OFF_STAGE;
    __half* hsm    = (__half*)(sm + OFF_HSM);
    float* wih_s   = sm + OFF_WIH;
    float* xbs     = sm + OFF_XBS;

    // init loads
    for (int i = tid; i < BT * SS * FF; i += NTHR) {
        int b = i / (SS * FF);
        int r = i - b * (SS * FF);
        xbs[b * 1176 + r] = xb[(size_t)(b0 + b) * (SS * FF) + r];
    }
    for (int i = tid; i < GG4; i += NTHR) {
        #pragma unroll
        for (int f = 0; f < FF; ++f) {
            wih_s[i * 9 + f] = Wih_e[i * FF + f];
        }
        wih_s[i * 9 + 7] = bih_e[i] + bhh_e[i];
        bdec_s[i] = bih_d[i] + bhh_d[i];
    }
    for (int i = tid; i < 1088; i += NTHR) {
        ((float*)hsm)[i] = 0.f;
    }
    for (int i = tid; i < SS; i += NTHR) {
        batt_s[i] = batt[i];
    }
    for (int i = tid; i < FF * HH; i += NTHR) {
        wout_s[i] = Wout[i];
    }
    if (tid < FF) {
        wfin_s[tid] = Wfin[tid];
        bout_s[tid] = bout[tid];
    }
    if (tid == 0) {
        bfin_s[0] = bfin[0];
    }
    for (int i = tid; i < BT * 8; i += NTHR) {
        int b = i >> 3;
        int f = i & 7;
        y_s[i] = (f < FF) ? xb[(size_t)(b0 + b) * (SS * FF) + (SS - 1) * FF + f] : 0.f;
    }

    // fragment register file (encoder: Whh_e, 128; decoder: i/f gates, 128)
    uint32_t frg[128];

    // encoder A-frags: Whh_e fp16; warp owns rows [wid*64, wid*64+64)
    #pragma unroll
    for (int mt = 0; mt < 4; ++mt) {
        #pragma unroll
        for (int kt = 0; kt < 8; ++kt) {
            int r0 = wid * 64 + mt * 16 + gid;
            int c0 = kt * 16 + tig * 2;
            float2 v00 = *(const float2*)(Whh_e + (size_t)(r0    ) * HH + c0    );
            float2 v10 = *(const float2*)(Whh_e + (size_t)(r0 + 8) * HH + c0    );
            float2 v01 = *(const float2*)(Whh_e + (size_t)(r0    ) * HH + c0 + 8);
            float2 v11 = *(const float2*)(Whh_e + (size_t)(r0 + 8) * HH + c0 + 8);
            frg[(mt * 8 + kt) * 4 + 0] = f2h2(v00.x, v00.y);
            frg[(mt * 8 + kt) * 4 + 1] = f2h2(v10.x, v10.y);
            frg[(mt * 8 + kt) * 4 + 2] = f2h2(v01.x, v01.y);
            frg[(mt * 8 + kt) * 4 + 3] = f2h2(v11.x, v11.y);
        }
    }
    __syncthreads();

    // ---- encoder: 168 HMMA LSTM steps ----
    const int aj = tid >> 1;
    const int bh = (tid & 1) << 3;
    const int mtW = aj >> 4;
    const int gidW = aj & 7;
    const int hi8W = (aj >> 3) & 1;
    float creg[8];
    #pragma unroll
    for (int q = 0; q < 8; ++q) {
        creg[q] = 0.f;
    }

    for (int s = 0; s < SS; ++s) {
        float acc[4][2][4];
        #pragma unroll
        for (int mt = 0; mt < 4; ++mt) {
            #pragma unroll
            for (int nt = 0; nt < 2; ++nt) {
                #pragma unroll
                for (int q = 0; q < 4; ++q) {
                    acc[mt][nt][q] = 0.f;
                }
            }
        }
        #pragma unroll
        for (int kt = 0; kt < 8; ++kt) {
            int kb = kt * 16 + tig * 2;
            uint32_t bA0 = *(const uint32_t*)(hsm + (gid    ) * 136 + kb    );
            uint32_t bA1 = *(const uint32_t*)(hsm + (gid    ) * 136 + kb + 8);
            uint32_t bB0 = *(const uint32_t*)(hsm + (gid + 8) * 136 + kb    );
            uint32_t bB1 = *(const uint32_t*)(hsm + (gid + 8) * 136 + kb + 8);
            #pragma unroll
            for (int mt = 0; mt < 4; ++mt) {
                mma16816(acc[mt][0], frg + (mt * 8 + kt) * 4, bA0, bA1);
                mma16816(acc[mt][1], frg + (mt * 8 + kt) * 4, bB0, bB1);
            }
        }
        #pragma unroll
        for (int mt = 0; mt < 4; ++mt) {
            #pragma unroll
            for (int nt = 0; nt < 2; ++nt) {
                int g0 = wid * 64 + mt * 16 + gid;
                int bb = nt * 8 + tig * 2;
                stage[g0 * 17 + bb]           = acc[mt][nt][0];
                stage[g0 * 17 + bb + 1]       = acc[mt][nt][1];
                stage[(g0 + 8) * 17 + bb]     = acc[mt][nt][2];
                stage[(g0 + 8) * 17 + bb + 1] = acc[mt][nt][3];
            }
        }
        __syncthreads();

        const int ktS = s >> 4;
        const int cS = s & 15;
        const int tigW = (cS >> 1) & 3;
        const int regW = (cS >> 3) * 2 + hi8W;
        const int laneW = gidW * 4 + tigW;
        const int innerW = ((ktS * 8 + mtW) * 32 + laneW) * 8 + regW * 2 + (cS & 1);

        #pragma unroll
        for (int bi = 0; bi < 8; ++bi) {
            int b = bh + bi;
            float xf[7];
            #pragma unroll
            for (int f = 0; f < FF; ++f) {
                xf[f] = xbs[b * 1176 + s * FF + f];
            }
            float pre[4];
            #pragma unroll
            for (int gt = 0; gt < 4; ++gt) {
                const float* wr = wih_s + (gt * 128 + aj) * 9;
                float a = wr[7];
                #pragma unroll
                for (int f = 0; f < FF; ++f) {
                    a += wr[f] * xf[f];
                }
                pre[gt] = a + stage[(gt * 128 + aj) * 17 + b];
            }
            float cc = sigf(pre[1]) * creg[bi] + sigf(pre[0]) * tanh_f(pre[2]);
            float hh = sigf(pre[3]) * tanh_f(cc);
            creg[bi] = cc;
            hsm[b * 136 + aj] = __float2half_rn(hh);
            g_encf[(size_t)(b0 + b) * 22528 + innerW] = __float2half_rn(hh);
            if (s == SS - 1) {
                h_s[b * HSTR + aj] = hh;
            }
        }
        __syncthreads();
    }

    // ---- decoder setup ----
    __half* watt16 = (__half*)(sm + OFF_WATT);
    float* scor_s  = sm + OFF_SCOR;
    __half* wdg16  = (__half*)(sm + OFF_WDG);
    // W_att fp16 tile [176][152], zero-padded
    for (int i = tid; i < 176 * 76; i += NTHR) {
        int r = i / 76;
        int c = (i - r * 76) * 2;
        float v0 = (r < SS && c < AAT) ? Watt[r * AAT + c] : 0.f;
        float v1 = (r < SS && c + 1 < AAT) ? Watt[r * AAT + c + 1] : 0.f;
        *(__half2*)(watt16 + r * ASTR + c) = __floats2half2_rn(v0, v1);
    }
    // g-gate weights [128 j][264: Wih k0..127 | Whh k0..127 | pad]
    for (int i = tid; i < 128 * 128; i += NTHR) {
        int j = i >> 7;
        int k = i & 127;
        wdg16[j * 264 + k]       = __float2half_rn(Wih_d[(256 + j) * HH + k]);
        wdg16[j * 264 + 128 + k] = __float2half_rn(Whh_d[(256 + j) * HH + k]);
    }
    // attn_in tile [h | y | 0]
    for (int i = tid; i < BT * ASTR; i += NTHR) {
        int b = i / ASTR;
        int c = i - b * ASTR;
        float v = 0.f;
        if (c < HH) {
            v = h_s[b * HSTR + c];
        } else if (c < AAT) {
            v = y_s[b * 8 + (c - HH)];
        }
        attin16[i] = __float2half_rn(v);
    }
    // softmax-weight tile zero (pad rows 168..175 stay 0 forever)
    for (int i = tid; i < BT * 176; i += NTHR) {
        ws16[i] = __float2half_rn(0.f);
    }

    // decoder A-frags (registers): gates i,f only; warp owns j in [wid*16, wid*16+16)
    #pragma unroll
    for (int g = 0; g < 2; ++g) {
        #pragma unroll
        for (int kt = 0; kt < 16; ++kt) {
            const float* W = (kt < 8) ? Wih_d : Whh_d;
            int R = g * 128 + wid * 16 + gid;
            int c0 = (kt & 7) * 16 + tig * 2;
            float2 v00 = *(const float2*)(W + (size_t)(R    ) * HH + c0    );
            float2 v10 = *(const float2*)(W + (size_t)(R + 8) * HH + c0    );
            float2 v01 = *(const float2*)(W + (size_t)(R    ) * HH + c0 + 8);
            float2 v11 = *(const float2*)(W + (size_t)(R + 8) * HH + c0 + 8);
            frg[(g * 16 + kt) * 4 + 0] = f2h2(v00.x, v00.y);
            frg[(g * 16 + kt) * 4 + 1] = f2h2(v10.x, v10.y);
            frg[(g * 16 + kt) * 4 + 2] = f2h2(v01.x, v01.y);
            frg[(g * 16 + kt) * 4 + 3] = f2h2(v11.x, v11.y);
        }
    }
    __syncthreads();

    // ---- decoder: 96 steps ----
    for (int p = 0; p < PP; ++p) {
        // 1) scores via HMMA: W_att(176x144) @ attn_in^T -> scor_s[b][s]
        {
            float sA[4] = {0.f, 0.f, 0.f, 0.f};
            float sB[4] = {0.f, 0.f, 0.f, 0.f};
            float sC[4] = {0.f, 0.f, 0.f, 0.f};
            float sD[4] = {0.f, 0.f, 0.f, 0.f};
            const int mt0 = wid;
            const int mt1 = 8 + wid;
            #pragma unroll
            for (int kt = 0; kt < 9; ++kt) {
                int kb = kt * 16 + tig * 2;
                uint32_t bA0 = *(const uint32_t*)(attin16 + (gid    ) * ASTR + kb    );
                uint32_t bA1 = *(const uint32_t*)(attin16 + (gid    ) * ASTR + kb + 8);
                uint32_t bB0 = *(const uint32_t*)(attin16 + (gid + 8) * ASTR + kb    );
                uint32_t bB1 = *(const uint32_t*)(attin16 + (gid + 8) * ASTR + kb + 8);
                uint32_t a[4];
                a[0] = *(const uint32_t*)(watt16 + (mt0 * 16 + gid    ) * ASTR + kb    );
                a[1] = *(const uint32_t*)(watt16 + (mt0 * 16 + 8 + gid) * ASTR + kb    );
                a[2] = *(const uint32_t*)(watt16 + (mt0 * 16 + gid    ) * ASTR + kb + 8);
                a[3] = *(const uint32_t*)(watt16 + (mt0 * 16 + 8 + gid) * ASTR + kb + 8);
                mma16816(sA, a, bA0, bA1);
                mma16816(sB, a, bB0, bB1);
                if (wid < 3) {
                    a[0] = *(const uint32_t*)(watt16 + (mt1 * 16 + gid    ) * ASTR + kb    );
                    a[1] = *(const uint32_t*)(watt16 + (mt1 * 16 + 8 + gid) * ASTR + kb    );
                    a[2] = *(const uint32_t*)(watt16 + (mt1 * 16 + gid    ) * ASTR + kb + 8);
                    a[3] = *(const uint32_t*)(watt16 + (mt1 * 16 + 8 + gid) * ASTR + kb + 8);
                    mma16816(sC, a, bA0, bA1);
                    mma16816(sD, a, bB0, bB1);
                }
            }
            #pragma unroll
            for (int q = 0; q < 4; ++q) {
                int si = mt0 * 16 + gid + ((q >> 1) << 3);
                int bb = tig * 2 + (q & 1);
                scor_s[bb * SS + si] = sA[q] + batt_s[si];
                scor_s[(bb + 8) * SS + si] = sB[q] + batt_s[si];
                if (wid < 3) {
                    int sj = mt1 * 16 + gid + ((q >> 1) << 3);
                    if (sj < SS) {
                        scor_s[bb * SS + sj] = sC[q] + batt_s[sj];
                        scor_s[(bb + 8) * SS + sj] = sD[q] + batt_s[sj];
                    }
                }
            }
        }
        __syncthreads();

        // 2) softmax -> ws16 (fp16)
        {
            int b = 2 * wid + (lane >> 4);
            int l16 = lane & 15;
            float mx = -1e30f;
            for (int s_ = l16; s_ < SS; s_ += 16) {
                mx = fmaxf(mx, scor_s[b * SS + s_]);
            }
            #pragma unroll
            for (int o = 8; o >= 1; o >>= 1) {
                mx = fmaxf(mx, __shfl_xor_sync(0xffffffffu, mx, o));
            }
            float sum = 0.f;
            for (int s_ = l16; s_ < SS; s_ += 16) {
                float e = __expf(scor_s[b * SS + s_] - mx);
                scor_s[b * SS + s_] = e;
                sum += e;
            }
            #pragma unroll
            for (int o = 8; o >= 1; o >>= 1) {
                sum += __shfl_xor_sync(0xffffffffu, sum, o);
            }
            float inv = __fdividef(1.f, sum);
            for (int s_ = l16; s_ < SS; s_ += 16) {
                float w = scor_s[b * SS + s_] * inv;
                ws16[b * 176 + s_] = __float2half_rn(w);
            }
        }
        __syncthreads();

        // 3) combine via HMMA, double-buffered LDG prefetch; warp does 2 batches
        {
            #pragma unroll
            for (int bi = 0; bi < 2; ++bi) {
                int b = wid * 2 + bi;
                const uint4* ap = reinterpret_cast<const uint4*>(g_encf + (size_t)(b0 + b) * 22528) + lane;
                const __half* wp = ws16 + b * 176;
                #pragma unroll
                for (int hm = 0; hm < 2; ++hm) {
                    float cc[4][4];
                    #pragma unroll
                    for (int m = 0; m < 4; ++m) {
                        #pragma unroll
                        for (int q = 0; q < 4; ++q) {
                            cc[m][q] = 0.f;
                        }
                    }
                    uint4 bufA[4];
                    uint4 bufB[4];
                    #pragma unroll
                    for (int m = 0; m < 4; ++m) {
                        bufA[m] = ap[(hm * 4 + m) * 32];
                    }
                    #pragma unroll
                    for (int kt = 0; kt < 11; ++kt) {
                        if (kt < 10) {
                            if ((kt & 1) == 0) {
                                #pragma unroll
                                for (int m = 0; m < 4; ++m) {
                                    bufB[m] = ap[((kt + 1) * 8 + hm * 4 + m) * 32];
                                }
                            } else {
                                #pragma unroll
                                for (int m = 0; m < 4; ++m) {
                                    bufA[m] = ap[((kt + 1) * 8 + hm * 4 + m) * 32];
                                }
                            }
                        }
                        uint32_t wb0 = *(const uint32_t*)(wp + kt * 16 + tig * 2    );
                        uint32_t wb1 = *(const uint32_t*)(wp + kt * 16 + 8 + tig * 2);
                        if ((kt & 1) == 0) {
                            #pragma unroll
                            for (int m = 0; m < 4; ++m) {
                                mma16816(cc[m], (const uint32_t*)&bufA[m], wb0, wb1);
                            }
                        } else {
                            #pragma unroll
                            for (int m = 0; m < 4; ++m) {
                                mma16816(cc[m], (const uint32_t*)&bufB[m], wb0, wb1);
                            }
                        }
                    }
                    if (tig == 0) {
                        #pragma unroll
                        for (int m = 0; m < 4; ++m) {
                            int h = (hm * 4 + m) * 16 + gid;
                            cmb16[b * ASTR + h]     = __float2half_rn(cc[m][0]);
                            cmb16[b * ASTR + h + 8] = __float2half_rn(cc[m][2]);
                        }
                    }
                }
            }
        }
        __syncthreads();

        // 4) gates via HMMA: [384x16x256] over [combine | prev_h]; g-gate frags from smem
        {
            float acc[3][2][4];
            #pragma unroll
            for (int g = 0; g < 3; ++g) {
                #pragma unroll
                for (int nt = 0; nt < 2; ++nt) {
                    #pragma unroll
                    for (int q = 0; q < 4; ++q) {
                        acc[g][nt][q] = 0.f;
                    }
                }
            }
            #pragma unroll
            for (int kt = 0; kt < 16; ++kt) {
                const __half* src = (kt < 8) ? cmb16 : attin16;
                int kb = (kt & 7) * 16 + tig * 2;
                uint32_t bA0 = *(const uint32_t*)(src + (gid    ) * ASTR + kb    );
                uint32_t bA1 = *(const uint32_t*)(src + (gid    ) * ASTR + kb + 8);
                uint32_t bB0 = *(const uint32_t*)(src + (gid + 8) * ASTR + kb    );
                uint32_t bB1 = *(const uint32_t*)(src + (gid + 8) * ASTR + kb + 8);
                uint32_t ag[4];
                const __half* wg = wdg16 + (wid * 16 + gid) * 264 + kt * 16 + tig * 2;
                ag[0] = *(const uint32_t*)(wg);
                ag[1] = *(const uint32_t*)(wg + 8 * 264);
                ag[2] = *(const uint32_t*)(wg + 8);
                ag[3] = *(const uint32_t*)(wg + 8 * 264 + 8);
                #pragma unroll
                for (int g = 0; g < 2; ++g) {
                    mma16816(acc[g][0], frg + (g * 16 + kt) * 4, bA0, bA1);
                    mma16816(acc[g][1], frg + (g * 16 + kt) * 4, bB0, bB1);
                }
                mma16816(acc[2][0], ag, bA0, bA1);
                mma16816(acc[2][1], ag, bB0, bB1);
            }
            __syncthreads();
            // epilogue: c_new = sig(f)*prev_h + sig(i)*tanh(g)
            #pragma unroll
            for (int nt = 0; nt < 2; ++nt) {
                #pragma unroll
                for (int q = 0; q < 4; ++q) {
                    int j = wid * 16 + gid + ((q >> 1) << 3);
                    int b = nt * 8 + tig * 2 + (q & 1);
                    float pi = acc[0][nt][q] + bdec_s[j];
                    float pf = acc[1][nt][q] + bdec_s[128 + j];
                    float pg = acc[2][nt][q] + bdec_s[256 + j];
                    float ph = h_s[b * HSTR + j];
                    float cn = sigf(pf) * ph + sigf(pi) * tanh_f(pg);
                    h_s[b * HSTR + j] = cn;
                    attin16[b * ASTR + j] = __float2half_rn(cn);
                }
            }
        }
        __syncthreads();

        // 5) out = c_new @ W_out^T + b_out; y -> attin16; final = out @ W_fin + b_fin
        if (tid < BT * FF) {
            int b = tid / FF;
            int f = tid - b * FF;
            float a = 0.f;
            #pragma unroll
            for (int j4 = 0; j4 < 32; ++j4) {
                float4 cv = *(const float4*)(h_s + b * HSTR + j4 * 4);
                float4 wv = *(const float4*)(wout_s + f * HH + j4 * 4);
                a += cv.x * wv.x + cv.y * wv.y + cv.z * wv.z + cv.w * wv.w;
            }
            float y = a + bout_s[f];
            y_s[b * 8 + f] = y;
            attin16[b * ASTR + HH + f] = __float2half_rn(y);
        }
        __syncthreads();
        if (tid < BT) {
            float a = bfin_s[0];
            #pragma unroll
            for (int f = 0; f < FF; ++f) {
                a += y_s[tid * 8 + f] * wfin_s[f];
            }
            out[(size_t)(b0 + tid) * PP + p] = a;
        }
        __syncthreads();
    }
}

extern "C" void kernel_launch(void* const* d_in, const int* in_sizes, int n_in,
                              void* d_out, int out_size)
{
    (void)in_sizes; (void)n_in; (void)out_size;
    cudaFuncSetAttribute(edk_kernel, cudaFuncAttributeMaxDynamicSharedMemorySize, SMEM_BYTES);
    edk_kernel<<<NCTA, NTHR, SMEM_BYTES>>>(
        (const float*)d_in[0],  (const float*)d_in[1],  (const float*)d_in[2],
        (const float*)d_in[3],  (const float*)d_in[4],  (const float*)d_in[5],
        (const float*)d_in[6],  (const float*)d_in[7],  (const float*)d_in[8],
        (const float*)d_in[9],  (const float*)d_in[10], (const float*)d_in[11],
        (const float*)d_in[12], (const float*)d_in[13], (const float*)d_in[14],
        (float*)d_out);
}